// round 1
// baseline (speedup 1.0000x reference)
#include <cuda_runtime.h>
#include <cstdint>
#include <cstddef>

// Problem constants
#define BB 2
#define SS 2048
#define DD 1024
#define HH 16
#define DH 64
#define MROWS (BB*SS)          // 4096
#define D4 (4*DD)              // 4096

// ---------------- scratch (device globals; no allocations) ----------------
__device__ float g_wq  [DD*DD];        // packed Wq [D, D] (col = h*64+e)
__device__ float g_qh  [MROWS*DD];     // q projection, [B,S,D] layout
__device__ float g_attn[MROWS*DD];     // attention output, [B,S,D]
__device__ float g_t1  [MROWS*DD];     // fc out + resid (pre-LN1)
__device__ float g_ln1 [MROWS*DD];     // LN1 output
__device__ float g_h   [MROWS*D4];     // MLP hidden (relu)
__device__ float g_t2  [MROWS*DD];     // mlp out + resid (pre-LN2)

// ---------------- pack wq_w [H,D,Dh] -> Wq [D, D] ----------------
__global__ void pack_wq_kernel(const float* __restrict__ wq_w, float* __restrict__ Wq) {
    int idx = blockIdx.x * blockDim.x + threadIdx.x;
    if (idx >= DD * DD) return;
    int d = idx / DD;
    int n = idx % DD;
    int h = n / DH;
    int e = n % DH;
    Wq[idx] = wq_w[((size_t)h * DD + d) * DH + e];
}

// ---------------- fp32 SGEMM 128x128x8, 256 threads, 8x8/thread ----------------
// C[M,N] = A[M,K] @ B[K,N] (+bias[n]) (+resid[m,n]) (relu)
template<bool RELU>
__global__ __launch_bounds__(256) void sgemm_kernel(
    const float* __restrict__ A, const float* __restrict__ Bm,
    const float* __restrict__ bias, const float* __restrict__ resid,
    float* __restrict__ C, int M, int N, int K)
{
    __shared__ float As[8][128];
    __shared__ float Bs[8][128];

    const int tid = threadIdx.x;
    const int tx = tid % 16;
    const int ty = tid / 16;
    const int row0 = blockIdx.y * 128;
    const int col0 = blockIdx.x * 128;

    float acc[8][8];
#pragma unroll
    for (int i = 0; i < 8; i++)
#pragma unroll
        for (int j = 0; j < 8; j++) acc[i][j] = 0.f;

    const int arow  = tid >> 1;          // 0..127
    const int acol4 = (tid & 1) * 4;     // 0 or 4
    const int brow  = tid >> 5;          // 0..7
    const int bcol4 = (tid & 31) * 4;    // 0..124

    for (int k0 = 0; k0 < K; k0 += 8) {
        float4 av = *(const float4*)(A + (size_t)(row0 + arow) * K + k0 + acol4);
        As[acol4 + 0][arow] = av.x;
        As[acol4 + 1][arow] = av.y;
        As[acol4 + 2][arow] = av.z;
        As[acol4 + 3][arow] = av.w;
        float4 bv = *(const float4*)(Bm + (size_t)(k0 + brow) * N + col0 + bcol4);
        *(float4*)&Bs[brow][bcol4] = bv;
        __syncthreads();
#pragma unroll
        for (int k = 0; k < 8; k++) {
            float a[8], b[8];
#pragma unroll
            for (int i = 0; i < 4; i++) {
                a[i]     = As[k][ty * 4 + i];
                a[4 + i] = As[k][64 + ty * 4 + i];
                b[i]     = Bs[k][tx * 4 + i];
                b[4 + i] = Bs[k][64 + tx * 4 + i];
            }
#pragma unroll
            for (int i = 0; i < 8; i++)
#pragma unroll
                for (int j = 0; j < 8; j++) acc[i][j] += a[i] * b[j];
        }
        __syncthreads();
    }

#pragma unroll
    for (int i = 0; i < 8; i++) {
        int r = row0 + ((i < 4) ? (ty * 4 + i) : (64 + ty * 4 + (i - 4)));
#pragma unroll
        for (int j = 0; j < 8; j++) {
            int c = col0 + ((j < 4) ? (tx * 4 + j) : (64 + tx * 4 + (j - 4)));
            float v = acc[i][j];
            if (bias)  v += bias[c];
            if (resid) v += resid[(size_t)r * N + c];
            if (RELU)  v = fmaxf(v, 0.f);
            C[(size_t)r * N + c] = v;
        }
    }
}

// ---------------- flash attention (Q=K=V=qh), fp32 ----------------
// grid: (S/64, H, B), block: 256. BM=64 queries, BN=32 keys/iter, Dh=64.
__global__ __launch_bounds__(256) void flash_kernel(
    const float* __restrict__ qh, float* __restrict__ out)
{
    __shared__ float Qs[64][64];   // queries (pre-scaled by 1/8)
    __shared__ float Kn[32][64];   // key tile, key-major (= V)
    __shared__ float Ke[64][33];   // key tile transposed (feature-major), padded
    __shared__ float Ps[64][32];   // probabilities

    const int qt = blockIdx.x;
    const int h  = blockIdx.y;
    const int b  = blockIdx.z;
    const int tid = threadIdx.x;
    const int tx = tid % 16;
    const int ty = tid / 16;

    const float* base = qh + (size_t)b * SS * DD + h * DH;
    const int q0 = qt * 64;

    // load Q tile (scaled by 1/sqrt(Dh) = 1/8)
    for (int i = tid; i < 64 * 16; i += 256) {
        int r = i / 16, c4 = (i % 16) * 4;
        float4 v = *(const float4*)(base + (size_t)(q0 + r) * DD + c4);
        v.x *= 0.125f; v.y *= 0.125f; v.z *= 0.125f; v.w *= 0.125f;
        *(float4*)&Qs[r][c4] = v;
    }

    float m_i[4], l_i[4], o[4][4];
#pragma unroll
    for (int i = 0; i < 4; i++) {
        m_i[i] = -1e30f; l_i[i] = 0.f;
#pragma unroll
        for (int j = 0; j < 4; j++) o[i][j] = 0.f;
    }

    for (int kt = 0; kt < SS / 32; kt++) {
        __syncthreads();   // protect Kn/Ke/Ps from previous iteration readers
        // load K tile [32 x 64] in both layouts
        for (int i = tid; i < 32 * 16; i += 256) {
            int r = i / 16, c4 = (i % 16) * 4;
            float4 v = *(const float4*)(base + (size_t)(kt * 32 + r) * DD + c4);
            *(float4*)&Kn[r][c4] = v;
            Ke[c4 + 0][r] = v.x; Ke[c4 + 1][r] = v.y;
            Ke[c4 + 2][r] = v.z; Ke[c4 + 3][r] = v.w;
        }
        __syncthreads();

        // S tile = Qs(64x64) @ Ke(64x32): thread covers rows ty*4+i, cols tx*2+j
        float s[4][2];
#pragma unroll
        for (int i = 0; i < 4; i++) { s[i][0] = 0.f; s[i][1] = 0.f; }
#pragma unroll 4
        for (int e = 0; e < 64; e++) {
            float b0 = Ke[e][tx * 2 + 0];
            float b1 = Ke[e][tx * 2 + 1];
#pragma unroll
            for (int i = 0; i < 4; i++) {
                float q = Qs[ty * 4 + i][e];
                s[i][0] += q * b0;
                s[i][1] += q * b1;
            }
        }

        // online softmax per row (reduce across 16 tx lanes)
#pragma unroll
        for (int i = 0; i < 4; i++) {
            float mx = fmaxf(s[i][0], s[i][1]);
#pragma unroll
            for (int off = 1; off < 16; off <<= 1)
                mx = fmaxf(mx, __shfl_xor_sync(0xffffffffu, mx, off));
            float mnew = fmaxf(m_i[i], mx);
            float p0 = __expf(s[i][0] - mnew);
            float p1 = __expf(s[i][1] - mnew);
            float sum = p0 + p1;
#pragma unroll
            for (int off = 1; off < 16; off <<= 1)
                sum += __shfl_xor_sync(0xffffffffu, sum, off);
            float alpha = __expf(m_i[i] - mnew);
            l_i[i] = l_i[i] * alpha + sum;
            m_i[i] = mnew;
#pragma unroll
            for (int j = 0; j < 4; j++) o[i][j] *= alpha;
            Ps[ty * 4 + i][tx * 2 + 0] = p0;
            Ps[ty * 4 + i][tx * 2 + 1] = p1;
        }
        __syncthreads();

        // O += Ps(64x32) @ Kn(32x64): thread rows ty*4+i, cols tx*4+j
#pragma unroll 4
        for (int kk = 0; kk < 32; kk++) {
            float b0 = Kn[kk][tx * 4 + 0];
            float b1 = Kn[kk][tx * 4 + 1];
            float b2 = Kn[kk][tx * 4 + 2];
            float b3 = Kn[kk][tx * 4 + 3];
#pragma unroll
            for (int i = 0; i < 4; i++) {
                float p = Ps[ty * 4 + i][kk];
                o[i][0] += p * b0;
                o[i][1] += p * b1;
                o[i][2] += p * b2;
                o[i][3] += p * b3;
            }
        }
    }

    // write normalized output into [B,S,D] layout (head h -> cols h*64..)
    float* op = out + ((size_t)b * SS + q0) * DD + h * DH;
#pragma unroll
    for (int i = 0; i < 4; i++) {
        float inv = 1.0f / l_i[i];
#pragma unroll
        for (int j = 0; j < 4; j++)
            op[(size_t)(ty * 4 + i) * DD + tx * 4 + j] = o[i][j] * inv;
    }
}

// ---------------- layernorm over last dim (D=1024), one block per row ----------------
__global__ __launch_bounds__(256) void ln_kernel(
    const float* __restrict__ in, const float* __restrict__ gw,
    const float* __restrict__ bw, float* __restrict__ out)
{
    const int row = blockIdx.x;
    const int tid = threadIdx.x;
    const float4 v = ((const float4*)(in + (size_t)row * DD))[tid];

    float s  = v.x + v.y + v.z + v.w;
    float sq = v.x * v.x + v.y * v.y + v.z * v.z + v.w * v.w;
#pragma unroll
    for (int off = 16; off > 0; off >>= 1) {
        s  += __shfl_down_sync(0xffffffffu, s,  off);
        sq += __shfl_down_sync(0xffffffffu, sq, off);
    }
    __shared__ float ssum[8], ssq[8];
    const int warp = tid / 32, lane = tid % 32;
    if (lane == 0) { ssum[warp] = s; ssq[warp] = sq; }
    __syncthreads();
    if (tid == 0) {
        float S = 0.f, Q = 0.f;
#pragma unroll
        for (int w = 0; w < 8; w++) { S += ssum[w]; Q += ssq[w]; }
        ssum[0] = S; ssq[0] = Q;
    }
    __syncthreads();
    const float mu  = ssum[0] * (1.0f / DD);
    const float var = ssq[0] * (1.0f / DD) - mu * mu;
    const float r   = rsqrtf(var + 1e-5f);

    const float4 g4 = ((const float4*)gw)[tid];
    const float4 b4 = ((const float4*)bw)[tid];
    float4 ov;
    ov.x = (v.x - mu) * r * g4.x + b4.x;
    ov.y = (v.y - mu) * r * g4.y + b4.y;
    ov.z = (v.z - mu) * r * g4.z + b4.z;
    ov.w = (v.w - mu) * r * g4.w + b4.w;
    ((float4*)(out + (size_t)row * DD))[tid] = ov;
}

// ---------------- launch ----------------
extern "C" void kernel_launch(void* const* d_in, const int* in_sizes, int n_in,
                              void* d_out, int out_size)
{
    const float* x     = (const float*)d_in[0];
    const float* wq_w  = (const float*)d_in[1];
    const float* wq_b  = (const float*)d_in[2];
    const float* fc_w  = (const float*)d_in[3];
    const float* fc_b  = (const float*)d_in[4];
    const float* ln1_g = (const float*)d_in[5];
    const float* ln1_b = (const float*)d_in[6];
    const float* w1    = (const float*)d_in[7];
    const float* b1    = (const float*)d_in[8];
    const float* w2    = (const float*)d_in[9];
    const float* b2    = (const float*)d_in[10];
    const float* ln2_g = (const float*)d_in[11];
    const float* ln2_b = (const float*)d_in[12];
    float* out = (float*)d_out;

    float *wq, *qh, *attn, *t1, *ln1, *hbuf, *t2;
    cudaGetSymbolAddress((void**)&wq,   g_wq);
    cudaGetSymbolAddress((void**)&qh,   g_qh);
    cudaGetSymbolAddress((void**)&attn, g_attn);
    cudaGetSymbolAddress((void**)&t1,   g_t1);
    cudaGetSymbolAddress((void**)&ln1,  g_ln1);
    cudaGetSymbolAddress((void**)&hbuf, g_h);
    cudaGetSymbolAddress((void**)&t2,   g_t2);

    // 1) pack Wq
    pack_wq_kernel<<<(DD * DD + 255) / 256, 256>>>(wq_w, wq);
    // 2) qh = x @ Wq + wq_b      [4096,1024]
    sgemm_kernel<false><<<dim3(DD / 128, MROWS / 128), 256>>>(x, wq, wq_b, nullptr, qh, MROWS, DD, DD);
    // 3) flash attention -> attn [B,S,D]
    flash_kernel<<<dim3(SS / 64, HH, BB), 256>>>(qh, attn);
    // 4) t1 = attn @ fc_w + fc_b + x
    sgemm_kernel<false><<<dim3(DD / 128, MROWS / 128), 256>>>(attn, fc_w, fc_b, x, t1, MROWS, DD, DD);
    // 5) ln1 = LN(t1)
    ln_kernel<<<MROWS, 256>>>(t1, ln1_g, ln1_b, ln1);
    // 6) h = relu(ln1 @ w1 + b1)  [4096,4096]
    sgemm_kernel<true><<<dim3(D4 / 128, MROWS / 128), 256>>>(ln1, w1, b1, nullptr, hbuf, MROWS, D4, DD);
    // 7) t2 = h @ w2 + b2 + ln1
    sgemm_kernel<false><<<dim3(DD / 128, MROWS / 128), 256>>>(hbuf, w2, b2, ln1, t2, MROWS, DD, D4);
    // 8) out = LN(t2)
    ln_kernel<<<MROWS, 256>>>(t2, ln2_g, ln2_b, out);
}

// round 3
// speedup vs baseline: 1.5728x; 1.5728x over previous
#include <cuda_runtime.h>
#include <cuda_bf16.h>
#include <cstdint>
#include <cstddef>

// Problem constants
#define BB 2
#define SS 2048
#define DD 1024
#define HH 16
#define DH 64
#define MROWS (BB*SS)          // 4096
#define D4 (4*DD)              // 4096

// ---------------- scratch (device globals; no allocations) ----------------
__device__ float g_wq  [DD*DD];
__device__ float g_qh  [MROWS*DD];
__device__ float g_attn[MROWS*DD];
__device__ float g_t1  [MROWS*DD];
__device__ float g_ln1 [MROWS*DD];
__device__ float g_h   [MROWS*D4];
__device__ float g_t2  [MROWS*DD];

// ================= helpers =================
__device__ __forceinline__ uint32_t smem_u32(const void* p) {
    uint32_t a;
    asm("{ .reg .u64 t; cvta.to.shared.u64 t, %1; cvt.u32.u64 %0, t; }" : "=r"(a) : "l"(p));
    return a;
}

// fp32 pair -> packed bf16x2 hi + packed bf16x2 lo (x in low half, y in high half)
__device__ __forceinline__ void cvt2(float x, float y, uint32_t& hi, uint32_t& lo) {
    uint32_t h;
    asm("cvt.rn.bf16x2.f32 %0, %1, %2;" : "=r"(h) : "f"(y), "f"(x));
    float rx = x - __uint_as_float(h << 16);
    float ry = y - __uint_as_float(h & 0xffff0000u);
    asm("cvt.rn.bf16x2.f32 %0, %1, %2;" : "=r"(lo) : "f"(ry), "f"(rx));
    hi = h;
}

__device__ __forceinline__ void ldsm4(uint32_t* r, uint32_t addr) {
    asm volatile("ldmatrix.sync.aligned.m8n8.x4.shared.b16 {%0,%1,%2,%3}, [%4];"
                 : "=r"(r[0]), "=r"(r[1]), "=r"(r[2]), "=r"(r[3]) : "r"(addr));
}
__device__ __forceinline__ void ldsm4t(uint32_t* r, uint32_t addr) {
    asm volatile("ldmatrix.sync.aligned.m8n8.x4.trans.shared.b16 {%0,%1,%2,%3}, [%4];"
                 : "=r"(r[0]), "=r"(r[1]), "=r"(r[2]), "=r"(r[3]) : "r"(addr));
}
__device__ __forceinline__ void mma16816(float* d, const uint32_t* a, uint32_t b0, uint32_t b1) {
    asm volatile(
        "mma.sync.aligned.m16n8k16.row.col.f32.bf16.bf16.f32 "
        "{%0,%1,%2,%3}, {%4,%5,%6,%7}, {%8,%9}, {%0,%1,%2,%3};"
        : "+f"(d[0]), "+f"(d[1]), "+f"(d[2]), "+f"(d[3])
        : "r"(a[0]), "r"(a[1]), "r"(a[2]), "r"(a[3]), "r"(b0), "r"(b1));
}

// ================= pack wq_w [H,D,Dh] -> Wq [D, D] =================
__global__ void pack_wq_kernel(const float* __restrict__ wq_w, float* __restrict__ Wq) {
    int idx = blockIdx.x * blockDim.x + threadIdx.x;
    if (idx >= DD * DD) return;
    int d = idx / DD;
    int n = idx % DD;
    int h = n / DH;
    int e = n % DH;
    Wq[idx] = wq_w[((size_t)h * DD + d) * DH + e];
}

// ================= bf16x3 HMMA GEMM =================
// C[M,N] = A[M,K] @ W[K,N] (+bias) (+resid) (relu), fp32 in/out.
// CTA = 128x128 tile, 8 warps (2m x 4n), warp = 64x32. K-slab 32 fp32, double buffered.
// SMEM per stage: Ahi[128][32]bf16 (8K, 64B rows, chunk^=(r>>1)&3),
//                 Alo (8K), Bhi[32][128]bf16 (8K, 256B rows, chunk^=(k&7)), Blo (8K).
#define STAGE_BYTES 32768
#define HMMA_SMEM (2 * STAGE_BYTES + 128)

__global__ __launch_bounds__(256, 1) void hmma_gemm_kernel(
    const float* __restrict__ A, const float* __restrict__ W,
    const float* __restrict__ bias, const float* __restrict__ resid,
    float* __restrict__ C, int M, int N, int K, int relu)
{
    extern __shared__ char dsm_raw[];
    uint32_t sraw = smem_u32(dsm_raw);
    uint32_t sb = (sraw + 127u) & ~127u;   // 128B aligned base

    const int tid = threadIdx.x;
    const int wid = tid >> 5;
    const int l   = tid & 31;
    const int wm  = wid >> 2;     // 0..1
    const int wn  = wid & 3;      // 0..3
    const int row0 = blockIdx.y * 128;
    const int col0 = blockIdx.x * 128;

    float acc[16][4];
#pragma unroll
    for (int i = 0; i < 16; i++)
#pragma unroll
        for (int j = 0; j < 4; j++) acc[i][j] = 0.f;

    // ---- global load index precompute ----
    // A items: idx -> r = idx>>3 (row 0..127), q = idx&7 (k quad)
    const int ar = tid >> 1;               // nope — recompute per item below
    (void)ar;

    // store-address helpers (byte offsets within a stage)
    auto a_st = [](uint32_t r, uint32_t q) -> uint32_t {
        uint32_t chunk = q >> 1, off = (q & 1) * 8;
        return r * 64 + (((chunk) ^ ((r >> 1) & 3)) << 4) + off;
    };
    auto b_st = [](uint32_t k, uint32_t n) -> uint32_t {   // n multiple of 4
        uint32_t chunk = n >> 3;
        return k * 256 + (((chunk) ^ (k & 7)) << 4) + (n & 7) * 2;
    };

    const int NS = K >> 5;   // stages of 32
    float4 av[4], bv[4];

    auto gload = [&](int s) {
        int k0 = s << 5;
#pragma unroll
        for (int i = 0; i < 4; i++) {
            int idx = tid + i * 256;
            int r = idx >> 3, q = idx & 7;
            av[i] = *(const float4*)(A + (size_t)(row0 + r) * K + k0 + q * 4);
        }
#pragma unroll
        for (int i = 0; i < 4; i++) {
            int idx = tid + i * 256;
            int k = idx >> 5, n4 = idx & 31;
            bv[i] = *(const float4*)(W + (size_t)(k0 + k) * N + col0 + n4 * 4);
        }
    };
    auto sstore = [&](int p) {
        uint32_t Ahi = sb + p * STAGE_BYTES;
        uint32_t Alo = Ahi + 8192;
        uint32_t Bhi = Ahi + 16384;
        uint32_t Blo = Ahi + 24576;
#pragma unroll
        for (int i = 0; i < 4; i++) {
            int idx = tid + i * 256;
            uint32_t r = idx >> 3, q = idx & 7;
            uint32_t h01, l01, h23, l23;
            cvt2(av[i].x, av[i].y, h01, l01);
            cvt2(av[i].z, av[i].w, h23, l23);
            uint32_t ad = a_st(r, q);
            asm volatile("st.shared.v2.b32 [%0], {%1,%2};" :: "r"(Ahi + ad), "r"(h01), "r"(h23));
            asm volatile("st.shared.v2.b32 [%0], {%1,%2};" :: "r"(Alo + ad), "r"(l01), "r"(l23));
        }
#pragma unroll
        for (int i = 0; i < 4; i++) {
            int idx = tid + i * 256;
            uint32_t k = idx >> 5, n4 = idx & 31;
            uint32_t h01, l01, h23, l23;
            cvt2(bv[i].x, bv[i].y, h01, l01);
            cvt2(bv[i].z, bv[i].w, h23, l23);
            uint32_t bd = b_st(k, n4 * 4);
            asm volatile("st.shared.v2.b32 [%0], {%1,%2};" :: "r"(Bhi + bd), "r"(h01), "r"(h23));
            asm volatile("st.shared.v2.b32 [%0], {%1,%2};" :: "r"(Blo + bd), "r"(l01), "r"(l23));
        }
    };

    // ---- ldmatrix address precompute ----
    const uint32_t l15 = l & 15;
    const uint32_t asw = (l15 >> 1) & 3;        // A swizzle selector (indep of frag)
    const uint32_t ack = l >> 4;                // A chunk add (0/1)
    const uint32_t bk7 = l & 7;                 // B row within 8
    const uint32_t bka = (l >> 4) * 8;          // B k add
    const uint32_t bna = ((l >> 3) & 1) * 8;    // B n add

    gload(0);
    sstore(0);
    __syncthreads();

    for (int s = 0; s < NS; s++) {
        int p = s & 1;
        if (s + 1 < NS) gload(s + 1);

        uint32_t Ahi = sb + p * STAGE_BYTES;
        uint32_t Alo = Ahi + 8192;
        uint32_t Bhi = Ahi + 16384;
        uint32_t Blo = Ahi + 24576;

#pragma unroll
        for (int kk16 = 0; kk16 < 2; kk16++) {
            uint32_t ah[4][4], al[4][4], bh[2][4], bl[2][4];
            uint32_t ac = (uint32_t)(kk16 * 2) + ack;   // k chunk (0..3)
#pragma unroll
            for (int i = 0; i < 4; i++) {
                uint32_t row = wm * 64 + i * 16 + l15;
                uint32_t ad = row * 64 + ((ac ^ asw) << 4);
                ldsm4(ah[i], Ahi + ad);
                ldsm4(al[i], Alo + ad);
            }
#pragma unroll
            for (int j2 = 0; j2 < 2; j2++) {
                uint32_t krow = (uint32_t)(kk16 * 16) + bka + bk7;
                uint32_t ncol = wn * 32 + j2 * 16 + bna;
                uint32_t bd = krow * 256 + (((ncol >> 3) ^ bk7) << 4);
                ldsm4t(bh[j2], Bhi + bd);
                ldsm4t(bl[j2], Blo + bd);
            }
#pragma unroll
            for (int i = 0; i < 4; i++) {
#pragma unroll
                for (int j = 0; j < 4; j++) {
                    int j2 = j >> 1, jj = j & 1;
                    float* d = acc[i * 4 + j];
                    mma16816(d, ah[i], bh[j2][jj], bh[j2][2 + jj]);
                    mma16816(d, ah[i], bl[j2][jj], bl[j2][2 + jj]);
                    mma16816(d, al[i], bh[j2][jj], bh[j2][2 + jj]);
                }
            }
        }
        __syncthreads();
        if (s + 1 < NS) {
            sstore((s + 1) & 1);
            __syncthreads();
        }
    }

    // ---- epilogue ----
    const int tq = l >> 2;          // 0..7
    const int tr = (l & 3) * 2;     // 0,2,4,6
#pragma unroll
    for (int j = 0; j < 4; j++) {
        int c = col0 + wn * 32 + j * 8 + tr;
        float bx = 0.f, by = 0.f;
        if (bias) { bx = bias[c]; by = bias[c + 1]; }
#pragma unroll
        for (int i = 0; i < 4; i++) {
            int m0 = row0 + wm * 64 + i * 16 + tq;
            float* d = acc[i * 4 + j];
            float2 v0 = make_float2(d[0] + bx, d[1] + by);
            float2 v1 = make_float2(d[2] + bx, d[3] + by);
            if (resid) {
                float2 r0 = *(const float2*)(resid + (size_t)m0 * N + c);
                float2 r1 = *(const float2*)(resid + (size_t)(m0 + 8) * N + c);
                v0.x += r0.x; v0.y += r0.y; v1.x += r1.x; v1.y += r1.y;
            }
            if (relu) {
                v0.x = fmaxf(v0.x, 0.f); v0.y = fmaxf(v0.y, 0.f);
                v1.x = fmaxf(v1.x, 0.f); v1.y = fmaxf(v1.y, 0.f);
            }
            *(float2*)(C + (size_t)m0 * N + c) = v0;
            *(float2*)(C + (size_t)(m0 + 8) * N + c) = v1;
        }
    }
}

// ================= flash attention (Q=K=V=qh), fp32 =================
__global__ __launch_bounds__(256) void flash_kernel(
    const float* __restrict__ qh, float* __restrict__ out)
{
    __shared__ float Qs[64][64];
    __shared__ float Kn[32][64];
    __shared__ float Ke[64][33];
    __shared__ float Ps[64][32];

    const int qt = blockIdx.x;
    const int h  = blockIdx.y;
    const int b  = blockIdx.z;
    const int tid = threadIdx.x;
    const int tx = tid % 16;
    const int ty = tid / 16;

    const float* base = qh + (size_t)b * SS * DD + h * DH;
    const int q0 = qt * 64;

    for (int i = tid; i < 64 * 16; i += 256) {
        int r = i / 16, c4 = (i % 16) * 4;
        float4 v = *(const float4*)(base + (size_t)(q0 + r) * DD + c4);
        v.x *= 0.125f; v.y *= 0.125f; v.z *= 0.125f; v.w *= 0.125f;
        *(float4*)&Qs[r][c4] = v;
    }

    float m_i[4], l_i[4], o[4][4];
#pragma unroll
    for (int i = 0; i < 4; i++) {
        m_i[i] = -1e30f; l_i[i] = 0.f;
#pragma unroll
        for (int j = 0; j < 4; j++) o[i][j] = 0.f;
    }

    for (int kt = 0; kt < SS / 32; kt++) {
        __syncthreads();
        for (int i = tid; i < 32 * 16; i += 256) {
            int r = i / 16, c4 = (i % 16) * 4;
            float4 v = *(const float4*)(base + (size_t)(kt * 32 + r) * DD + c4);
            *(float4*)&Kn[r][c4] = v;
            Ke[c4 + 0][r] = v.x; Ke[c4 + 1][r] = v.y;
            Ke[c4 + 2][r] = v.z; Ke[c4 + 3][r] = v.w;
        }
        __syncthreads();

        float s[4][2];
#pragma unroll
        for (int i = 0; i < 4; i++) { s[i][0] = 0.f; s[i][1] = 0.f; }
#pragma unroll 4
        for (int e = 0; e < 64; e++) {
            float b0 = Ke[e][tx * 2 + 0];
            float b1 = Ke[e][tx * 2 + 1];
#pragma unroll
            for (int i = 0; i < 4; i++) {
                float q = Qs[ty * 4 + i][e];
                s[i][0] += q * b0;
                s[i][1] += q * b1;
            }
        }

#pragma unroll
        for (int i = 0; i < 4; i++) {
            float mx = fmaxf(s[i][0], s[i][1]);
#pragma unroll
            for (int off = 1; off < 16; off <<= 1)
                mx = fmaxf(mx, __shfl_xor_sync(0xffffffffu, mx, off));
            float mnew = fmaxf(m_i[i], mx);
            float p0 = __expf(s[i][0] - mnew);
            float p1 = __expf(s[i][1] - mnew);
            float sum = p0 + p1;
#pragma unroll
            for (int off = 1; off < 16; off <<= 1)
                sum += __shfl_xor_sync(0xffffffffu, sum, off);
            float alpha = __expf(m_i[i] - mnew);
            l_i[i] = l_i[i] * alpha + sum;
            m_i[i] = mnew;
#pragma unroll
            for (int j = 0; j < 4; j++) o[i][j] *= alpha;
            Ps[ty * 4 + i][tx * 2 + 0] = p0;
            Ps[ty * 4 + i][tx * 2 + 1] = p1;
        }
        __syncthreads();

#pragma unroll 4
        for (int kk = 0; kk < 32; kk++) {
            float b0 = Kn[kk][tx * 4 + 0];
            float b1 = Kn[kk][tx * 4 + 1];
            float b2 = Kn[kk][tx * 4 + 2];
            float b3 = Kn[kk][tx * 4 + 3];
#pragma unroll
            for (int i = 0; i < 4; i++) {
                float p = Ps[ty * 4 + i][kk];
                o[i][0] += p * b0;
                o[i][1] += p * b1;
                o[i][2] += p * b2;
                o[i][3] += p * b3;
            }
        }
    }

    float* op = out + ((size_t)b * SS + q0) * DD + h * DH;
#pragma unroll
    for (int i = 0; i < 4; i++) {
        float inv = 1.0f / l_i[i];
#pragma unroll
        for (int j = 0; j < 4; j++)
            op[(size_t)(ty * 4 + i) * DD + tx * 4 + j] = o[i][j] * inv;
    }
}

// ================= layernorm =================
__global__ __launch_bounds__(256) void ln_kernel(
    const float* __restrict__ in, const float* __restrict__ gw,
    const float* __restrict__ bw, float* __restrict__ out)
{
    const int row = blockIdx.x;
    const int tid = threadIdx.x;
    const float4 v = ((const float4*)(in + (size_t)row * DD))[tid];

    float s  = v.x + v.y + v.z + v.w;
    float sq = v.x * v.x + v.y * v.y + v.z * v.z + v.w * v.w;
#pragma unroll
    for (int off = 16; off > 0; off >>= 1) {
        s  += __shfl_down_sync(0xffffffffu, s,  off);
        sq += __shfl_down_sync(0xffffffffu, sq, off);
    }
    __shared__ float ssum[8], ssq[8];
    const int warp = tid / 32, lane = tid % 32;
    if (lane == 0) { ssum[warp] = s; ssq[warp] = sq; }
    __syncthreads();
    if (tid == 0) {
        float S = 0.f, Q = 0.f;
#pragma unroll
        for (int w = 0; w < 8; w++) { S += ssum[w]; Q += ssq[w]; }
        ssum[0] = S; ssq[0] = Q;
    }
    __syncthreads();
    const float mu  = ssum[0] * (1.0f / DD);
    const float var = ssq[0] * (1.0f / DD) - mu * mu;
    const float r   = rsqrtf(var + 1e-5f);

    const float4 g4 = ((const float4*)gw)[tid];
    const float4 b4 = ((const float4*)bw)[tid];
    float4 ov;
    ov.x = (v.x - mu) * r * g4.x + b4.x;
    ov.y = (v.y - mu) * r * g4.y + b4.y;
    ov.z = (v.z - mu) * r * g4.z + b4.z;
    ov.w = (v.w - mu) * r * g4.w + b4.w;
    ((float4*)(out + (size_t)row * DD))[tid] = ov;
}

// ================= launch =================
extern "C" void kernel_launch(void* const* d_in, const int* in_sizes, int n_in,
                              void* d_out, int out_size)
{
    const float* x     = (const float*)d_in[0];
    const float* wq_w  = (const float*)d_in[1];
    const float* wq_b  = (const float*)d_in[2];
    const float* fc_w  = (const float*)d_in[3];
    const float* fc_b  = (const float*)d_in[4];
    const float* ln1_g = (const float*)d_in[5];
    const float* ln1_b = (const float*)d_in[6];
    const float* w1    = (const float*)d_in[7];
    const float* b1    = (const float*)d_in[8];
    const float* w2    = (const float*)d_in[9];
    const float* b2    = (const float*)d_in[10];
    const float* ln2_g = (const float*)d_in[11];
    const float* ln2_b = (const float*)d_in[12];
    float* out = (float*)d_out;

    float *wq, *qh, *attn, *t1, *ln1, *hbuf, *t2;
    cudaGetSymbolAddress((void**)&wq,   g_wq);
    cudaGetSymbolAddress((void**)&qh,   g_qh);
    cudaGetSymbolAddress((void**)&attn, g_attn);
    cudaGetSymbolAddress((void**)&t1,   g_t1);
    cudaGetSymbolAddress((void**)&ln1,  g_ln1);
    cudaGetSymbolAddress((void**)&hbuf, g_h);
    cudaGetSymbolAddress((void**)&t2,   g_t2);

    cudaFuncSetAttribute(hmma_gemm_kernel, cudaFuncAttributeMaxDynamicSharedMemorySize, HMMA_SMEM);

    // 1) pack Wq
    pack_wq_kernel<<<(DD * DD + 255) / 256, 256>>>(wq_w, wq);
    // 2) qh = x @ Wq + wq_b
    hmma_gemm_kernel<<<dim3(DD / 128, MROWS / 128), 256, HMMA_SMEM>>>(
        x, wq, wq_b, nullptr, qh, MROWS, DD, DD, 0);
    // 3) flash attention
    flash_kernel<<<dim3(SS / 64, HH, BB), 256>>>(qh, attn);
    // 4) t1 = attn @ fc_w + fc_b + x
    hmma_gemm_kernel<<<dim3(DD / 128, MROWS / 128), 256, HMMA_SMEM>>>(
        attn, fc_w, fc_b, x, t1, MROWS, DD, DD, 0);
    // 5) ln1 = LN(t1)
    ln_kernel<<<MROWS, 256>>>(t1, ln1_g, ln1_b, ln1);
    // 6) h = relu(ln1 @ w1 + b1)
    hmma_gemm_kernel<<<dim3(D4 / 128, MROWS / 128), 256, HMMA_SMEM>>>(
        ln1, w1, b1, nullptr, hbuf, MROWS, D4, DD, 1);
    // 7) t2 = h @ w2 + b2 + ln1
    hmma_gemm_kernel<<<dim3(DD / 128, MROWS / 128), 256, HMMA_SMEM>>>(
        hbuf, w2, b2, ln1, t2, MROWS, DD, D4, 0);
    // 8) out = LN(t2)
    ln_kernel<<<MROWS, 256>>>(t2, ln2_g, ln2_b, out);
}

// round 4
// speedup vs baseline: 2.3330x; 1.4833x over previous
#include <cuda_runtime.h>
#include <cuda_bf16.h>
#include <cstdint>
#include <cstddef>

// Problem constants
#define BB 2
#define SS 2048
#define DD 1024
#define HH 16
#define DH 64
#define MROWS (BB*SS)          // 4096
#define D4 (4*DD)              // 4096
#define WSEG 1048576           // 1M elements per D*D weight

// ---------------- scratch (device globals; no allocations) ----------------
__device__ float g_wq  [DD*DD];                 // packed Wq fp32
__device__ __nv_bfloat16 g_whi[10*WSEG];        // wq | fc | w1 | w2 (hi)
__device__ __nv_bfloat16 g_wlo[10*WSEG];        // (lo)
__device__ __nv_bfloat16 g_qhi[MROWS*DD];       // qh hi
__device__ __nv_bfloat16 g_qlo[MROWS*DD];       // qh lo
__device__ float g_attn[MROWS*DD];
__device__ float g_t1  [MROWS*DD];
__device__ float g_ln1 [MROWS*DD];
__device__ float g_h   [MROWS*D4];
__device__ float g_t2  [MROWS*DD];

// ================= helpers =================
__device__ __forceinline__ uint32_t smem_u32(const void* p) {
    uint32_t a;
    asm("{ .reg .u64 t; cvta.to.shared.u64 t, %1; cvt.u32.u64 %0, t; }" : "=r"(a) : "l"(p));
    return a;
}
__device__ __forceinline__ float ex2(float x) {
    float y; asm("ex2.approx.ftz.f32 %0, %1;" : "=f"(y) : "f"(x)); return y;
}
// fp32 pair -> packed bf16x2 hi + lo (x low half, y high half)
__device__ __forceinline__ void cvt2(float x, float y, uint32_t& hi, uint32_t& lo) {
    uint32_t h;
    asm("cvt.rn.bf16x2.f32 %0, %1, %2;" : "=r"(h) : "f"(y), "f"(x));
    float rx = x - __uint_as_float(h << 16);
    float ry = y - __uint_as_float(h & 0xffff0000u);
    asm("cvt.rn.bf16x2.f32 %0, %1, %2;" : "=r"(lo) : "f"(ry), "f"(rx));
    hi = h;
}
__device__ __forceinline__ void ldsm4(uint32_t* r, uint32_t addr) {
    asm volatile("ldmatrix.sync.aligned.m8n8.x4.shared.b16 {%0,%1,%2,%3}, [%4];"
                 : "=r"(r[0]), "=r"(r[1]), "=r"(r[2]), "=r"(r[3]) : "r"(addr));
}
__device__ __forceinline__ void ldsm4t(uint32_t* r, uint32_t addr) {
    asm volatile("ldmatrix.sync.aligned.m8n8.x4.trans.shared.b16 {%0,%1,%2,%3}, [%4];"
                 : "=r"(r[0]), "=r"(r[1]), "=r"(r[2]), "=r"(r[3]) : "r"(addr));
}
__device__ __forceinline__ void mma16816(float* d, const uint32_t* a, uint32_t b0, uint32_t b1) {
    asm volatile(
        "mma.sync.aligned.m16n8k16.row.col.f32.bf16.bf16.f32 "
        "{%0,%1,%2,%3}, {%4,%5,%6,%7}, {%8,%9}, {%0,%1,%2,%3};"
        : "+f"(d[0]), "+f"(d[1]), "+f"(d[2]), "+f"(d[3])
        : "r"(a[0]), "r"(a[1]), "r"(a[2]), "r"(a[3]), "r"(b0), "r"(b1));
}
__device__ __forceinline__ void cp16(uint32_t dst, const void* src) {
    asm volatile("cp.async.cg.shared.global [%0], [%1], 16;" :: "r"(dst), "l"(src) : "memory");
}
#define CP_COMMIT() asm volatile("cp.async.commit_group;" ::: "memory")
#define CP_WAIT0()  asm volatile("cp.async.wait_group 0;" ::: "memory")
#define CP_WAIT1()  asm volatile("cp.async.wait_group 1;" ::: "memory")

// ================= pack wq_w [H,D,Dh] -> Wq [D, D] =================
__global__ void pack_wq_kernel(const float* __restrict__ wq_w, float* __restrict__ Wq) {
    int idx = blockIdx.x * blockDim.x + threadIdx.x;
    if (idx >= DD * DD) return;
    int d = idx / DD;
    int n = idx % DD;
    int h = n / DH;
    int e = n % DH;
    Wq[idx] = wq_w[((size_t)h * DD + d) * DH + e];
}

// ================= fp32 -> bf16 hi/lo splitter =================
__global__ void conv_split_kernel(const float* __restrict__ src,
                                  __nv_bfloat16* __restrict__ hi,
                                  __nv_bfloat16* __restrict__ lo, int n4) {
    int i = blockIdx.x * blockDim.x + threadIdx.x;
    if (i >= n4) return;
    float4 v = ((const float4*)src)[i];
    uint32_t h01, l01, h23, l23;
    cvt2(v.x, v.y, h01, l01);
    cvt2(v.z, v.w, h23, l23);
    uint32_t* hp = (uint32_t*)hi + (size_t)i * 2;
    uint32_t* lp = (uint32_t*)lo + (size_t)i * 2;
    hp[0] = h01; hp[1] = h23;
    lp[0] = l01; lp[1] = l23;
}

// ================= bf16x3 HMMA GEMM (512 threads, warp tile 32x32) =================
// C = A[M,K](fp32) @ W(bf16 hi/lo) (+bias) (+resid) (relu), or bf16-split output.
// CTA 128x128, 16 warps (4m x 4n). K-slab 32, A converted in-kernel, B via cp.async.
#define STAGE_BYTES 32768
#define HMMA_SMEM (2 * STAGE_BYTES + 128)

__global__ __launch_bounds__(512, 1) void hmma_gemm_kernel(
    const float* __restrict__ A,
    const __nv_bfloat16* __restrict__ Whi, const __nv_bfloat16* __restrict__ Wlo,
    const float* __restrict__ bias, const float* __restrict__ resid,
    float* __restrict__ C, __nv_bfloat16* __restrict__ Chi, __nv_bfloat16* __restrict__ Clo,
    int M, int N, int K, int relu)
{
    extern __shared__ char dsm_raw[];
    uint32_t sraw = smem_u32(dsm_raw);
    uint32_t sb = (sraw + 127u) & ~127u;

    const int tid = threadIdx.x;
    const int wid = tid >> 5;
    const int l   = tid & 31;
    const int wm  = wid >> 2;     // 0..3
    const int wn  = wid & 3;      // 0..3
    const int row0 = blockIdx.y * 128;
    const int col0 = blockIdx.x * 128;

    float acc[8][4];
#pragma unroll
    for (int i = 0; i < 8; i++)
#pragma unroll
        for (int j = 0; j < 4; j++) acc[i][j] = 0.f;

    const int NS = K >> 5;
    float4 av[2];

    // A global load (regs)
    auto gloadA = [&](int s) {
        int k0 = s << 5;
#pragma unroll
        for (int i = 0; i < 2; i++) {
            int idx = tid + i * 512;
            int r = idx >> 3, q = idx & 7;
            av[i] = *(const float4*)(A + (size_t)(row0 + r) * K + k0 + q * 4);
        }
    };
    // A convert + smem store
    auto sstoreA = [&](int p) {
        uint32_t Ahi = sb + p * STAGE_BYTES;
        uint32_t Alo = Ahi + 8192;
#pragma unroll
        for (int i = 0; i < 2; i++) {
            int idx = tid + i * 512;
            uint32_t r = idx >> 3, q = idx & 7;
            uint32_t h01, l01, h23, l23;
            cvt2(av[i].x, av[i].y, h01, l01);
            cvt2(av[i].z, av[i].w, h23, l23);
            uint32_t ad = r * 64 + (((q >> 1) ^ ((r >> 1) & 3)) << 4) + (q & 1) * 8;
            asm volatile("st.shared.v2.b32 [%0], {%1,%2};" :: "r"(Ahi + ad), "r"(h01), "r"(h23));
            asm volatile("st.shared.v2.b32 [%0], {%1,%2};" :: "r"(Alo + ad), "r"(l01), "r"(l23));
        }
    };
    // B cp.async (bf16 pre-converted)
    auto cpB = [&](int s, int p) {
        uint32_t Bhi = sb + p * STAGE_BYTES + 16384;
        uint32_t Blo = Bhi + 8192;
        int k0 = s << 5;
        uint32_t k = (uint32_t)tid >> 4, c = (uint32_t)tid & 15;
        uint32_t off = k * 256 + ((c ^ (k & 7)) << 4);
        const __nv_bfloat16* sh = Whi + (size_t)(k0 + k) * N + col0 + c * 8;
        const __nv_bfloat16* sl = Wlo + (size_t)(k0 + k) * N + col0 + c * 8;
        cp16(Bhi + off, sh);
        cp16(Blo + off, sl);
    };

    const uint32_t l15 = l & 15;
    const uint32_t asw = ((l15 >> 1) & 3);
    const uint32_t ack = (uint32_t)(l >> 4);
    const uint32_t bk7 = (uint32_t)(l & 7);
    const uint32_t bka = (uint32_t)(l >> 4) * 8;
    const uint32_t bna = (uint32_t)((l >> 3) & 1) * 8;

    gloadA(0);
    cpB(0, 0);
    CP_COMMIT();
    sstoreA(0);
    CP_WAIT0();
    __syncthreads();

    for (int s = 0; s < NS; s++) {
        int p = s & 1;
        if (s + 1 < NS) gloadA(s + 1);

        uint32_t Ahi = sb + p * STAGE_BYTES;
        uint32_t Alo = Ahi + 8192;
        uint32_t Bhi = Ahi + 16384;
        uint32_t Blo = Ahi + 24576;

#pragma unroll
        for (int kk16 = 0; kk16 < 2; kk16++) {
            uint32_t ah[2][4], al[2][4], bh[2][4], bl[2][4];
            uint32_t ac = (uint32_t)(kk16 * 2) + ack;
#pragma unroll
            for (int i = 0; i < 2; i++) {
                uint32_t row = wm * 32 + i * 16 + l15;
                uint32_t ad = row * 64 + (((ac) ^ asw) << 4);
                // NOTE: swizzle selector must match store: (row>>1)&3
                ad = row * 64 + ((ac ^ ((row >> 1) & 3)) << 4);
                ldsm4(ah[i], Ahi + ad);
                ldsm4(al[i], Alo + ad);
            }
#pragma unroll
            for (int j2 = 0; j2 < 2; j2++) {
                uint32_t krow = (uint32_t)(kk16 * 16) + bka + bk7;
                uint32_t ncol = wn * 32 + j2 * 16 + bna;
                uint32_t bd = krow * 256 + (((ncol >> 3) ^ bk7) << 4);
                ldsm4t(bh[j2], Bhi + bd);
                ldsm4t(bl[j2], Blo + bd);
            }
#pragma unroll
            for (int i = 0; i < 2; i++) {
#pragma unroll
                for (int j = 0; j < 4; j++) {
                    int j2 = j >> 1, jj = j & 1;
                    float* d = acc[i * 4 + j];
                    mma16816(d, ah[i], bh[j2][jj], bh[j2][2 + jj]);
                    mma16816(d, ah[i], bl[j2][jj], bl[j2][2 + jj]);
                    mma16816(d, al[i], bh[j2][jj], bh[j2][2 + jj]);
                }
            }
        }
        __syncthreads();
        if (s + 1 < NS) {
            int b = (s + 1) & 1;
            cpB(s + 1, b);
            CP_COMMIT();
            sstoreA(b);
            CP_WAIT0();
            __syncthreads();
        }
    }

    // ---- epilogue ----
    const int tq = l >> 2;
    const int tr = (l & 3) * 2;
#pragma unroll
    for (int j = 0; j < 4; j++) {
        int c = col0 + wn * 32 + j * 8 + tr;
        float bx = 0.f, by = 0.f;
        if (bias) { bx = bias[c]; by = bias[c + 1]; }
#pragma unroll
        for (int i = 0; i < 2; i++) {
            int m0 = row0 + wm * 32 + i * 16 + tq;
            float* d = acc[i * 4 + j];
            float v0x = d[0] + bx, v0y = d[1] + by;
            float v1x = d[2] + bx, v1y = d[3] + by;
            if (Chi) {
                uint32_t h0, l0, h1, l1;
                cvt2(v0x, v0y, h0, l0);
                cvt2(v1x, v1y, h1, l1);
                *(uint32_t*)((uint16_t*)Chi + (size_t)m0 * N + c) = h0;
                *(uint32_t*)((uint16_t*)Clo + (size_t)m0 * N + c) = l0;
                *(uint32_t*)((uint16_t*)Chi + (size_t)(m0 + 8) * N + c) = h1;
                *(uint32_t*)((uint16_t*)Clo + (size_t)(m0 + 8) * N + c) = l1;
            } else {
                if (resid) {
                    float2 r0 = *(const float2*)(resid + (size_t)m0 * N + c);
                    float2 r1 = *(const float2*)(resid + (size_t)(m0 + 8) * N + c);
                    v0x += r0.x; v0y += r0.y; v1x += r1.x; v1y += r1.y;
                }
                if (relu) {
                    v0x = fmaxf(v0x, 0.f); v0y = fmaxf(v0y, 0.f);
                    v1x = fmaxf(v1x, 0.f); v1y = fmaxf(v1y, 0.f);
                }
                *(float2*)(C + (size_t)m0 * N + c) = make_float2(v0x, v0y);
                *(float2*)(C + (size_t)(m0 + 8) * N + c) = make_float2(v1x, v1y);
            }
        }
    }
}

// ================= flash attention, HMMA bf16x3 (Q=K=V) =================
// grid (S/128, H, B), 256 threads (8 warps x 16 queries). Keys in tiles of 128.
// SMEM: Qhi(16K) Qlo(16K) | K buf0 hi/lo (32K) | K buf1 hi/lo (32K) = 96KB
#define FLASH_SMEM (96 * 1024 + 128)
#define SCALE2 0.18033688011112042f   /* log2(e)/8 */

__global__ __launch_bounds__(256, 1) void flash_hmma_kernel(
    const __nv_bfloat16* __restrict__ qhi, const __nv_bfloat16* __restrict__ qlo,
    float* __restrict__ out)
{
    extern __shared__ char dsm_raw[];
    uint32_t sraw = smem_u32(dsm_raw);
    uint32_t sb = (sraw + 127u) & ~127u;

    const int tid = threadIdx.x;
    const int w   = tid >> 5;
    const int l   = tid & 31;
    const int q0  = blockIdx.x * 128;
    const int h   = blockIdx.y;
    const int b   = blockIdx.z;

    const uint32_t Qhi = sb, Qlo = sb + 16384;
    const size_t gbase = (size_t)b * SS * DD + h * DH;   // element offset into [B*S, D]

    // prologue: Q + K0 as group 0
    {
#pragma unroll
        for (int i = 0; i < 4; i++) {
            int idx = tid + i * 256;
            uint32_t r = idx >> 3, c = idx & 7;
            uint32_t off = r * 128 + ((c ^ (r & 7)) << 4);
            const __nv_bfloat16* sh = qhi + gbase + (size_t)(q0 + r) * DD + c * 8;
            const __nv_bfloat16* sl = qlo + gbase + (size_t)(q0 + r) * DD + c * 8;
            cp16(Qhi + off, sh);
            cp16(Qlo + off, sl);
            const __nv_bfloat16* kh = qhi + gbase + (size_t)r * DD + c * 8;   // kt=0
            const __nv_bfloat16* kl = qlo + gbase + (size_t)r * DD + c * 8;
            cp16(sb + 32768 + off, kh);
            cp16(sb + 32768 + 16384 + off, kl);
        }
        CP_COMMIT();
    }

    uint32_t aqh[4][4], aql[4][4];   // resident Q fragments (4 ksteps)
    float S[16][4];
    float O[8][4];
    float m0 = -1e30f, m1 = -1e30f, l0 = 0.f, l1 = 0.f;
#pragma unroll
    for (int i = 0; i < 8; i++)
#pragma unroll
        for (int j = 0; j < 4; j++) O[i][j] = 0.f;

    const uint32_t l15 = l & 15;
    const uint32_t keyoff = (uint32_t)((l & 7) + ((l >> 3) & 1) * 8);
    const uint32_t kcadd  = (uint32_t)(l >> 4);
    const uint32_t vk7    = (uint32_t)(l & 7);
    const uint32_t vka    = (uint32_t)(l >> 4) * 8;
    const uint32_t vna    = (uint32_t)((l >> 3) & 1);

    const int NT = SS / 128;
    for (int kt = 0; kt < NT; kt++) {
        int p = kt & 1;
        __syncthreads();   // all warps done with buf p^1 reads (iter kt-1)
        if (kt + 1 < NT) {
            uint32_t Kd = sb + 32768 + (uint32_t)(p ^ 1) * 32768u;
#pragma unroll
            for (int i = 0; i < 4; i++) {
                int idx = tid + i * 256;
                uint32_t r = idx >> 3, c = idx & 7;
                uint32_t off = r * 128 + ((c ^ (r & 7)) << 4);
                const __nv_bfloat16* kh = qhi + gbase + (size_t)((kt + 1) * 128 + r) * DD + c * 8;
                const __nv_bfloat16* kl = qlo + gbase + (size_t)((kt + 1) * 128 + r) * DD + c * 8;
                cp16(Kd + off, kh);
                cp16(Kd + 16384 + off, kl);
            }
            CP_COMMIT();
            CP_WAIT1();
        } else {
            CP_WAIT0();
        }
        __syncthreads();   // buf p (and Q on kt==0) visible to all

        if (kt == 0) {
            // load resident Q fragments
#pragma unroll
            for (int ks = 0; ks < 4; ks++) {
                uint32_t row = (uint32_t)(w * 16) + l15;
                uint32_t ch = (uint32_t)(ks * 2) + kcadd;
                uint32_t ad = row * 128 + ((ch ^ (row & 7)) << 4);
                ldsm4(aqh[ks], Qhi + ad);
                ldsm4(aql[ks], Qlo + ad);
            }
        }

        uint32_t Kh = sb + 32768 + (uint32_t)p * 32768u;
        uint32_t Kl = Kh + 16384;

        // ---- S = Q @ K^T ----
#pragma unroll
        for (int nt = 0; nt < 16; nt++)
#pragma unroll
            for (int c = 0; c < 4; c++) S[nt][c] = 0.f;
#pragma unroll
        for (int ks = 0; ks < 4; ks++) {
#pragma unroll
            for (int nb = 0; nb < 8; nb++) {
                uint32_t key = (uint32_t)(nb * 16) + keyoff;
                uint32_t ch = (uint32_t)(ks * 2) + kcadd;
                uint32_t ad = key * 128 + ((ch ^ (key & 7)) << 4);
                uint32_t bh[4], bl[4];
                ldsm4(bh, Kh + ad);
                ldsm4(bl, Kl + ad);
#pragma unroll
                for (int jj = 0; jj < 2; jj++) {
                    float* d = S[nb * 2 + jj];
                    mma16816(d, aqh[ks], bh[jj], bh[2 + jj]);
                    mma16816(d, aqh[ks], bl[jj], bl[2 + jj]);
                    mma16816(d, aql[ks], bh[jj], bh[2 + jj]);
                }
            }
        }

        // ---- online softmax (rows l>>2 and l>>2+8; 4 lanes per row) ----
        float mx0 = -1e30f, mx1 = -1e30f;
#pragma unroll
        for (int nt = 0; nt < 16; nt++) {
            mx0 = fmaxf(mx0, fmaxf(S[nt][0], S[nt][1]));
            mx1 = fmaxf(mx1, fmaxf(S[nt][2], S[nt][3]));
        }
        mx0 = fmaxf(mx0, __shfl_xor_sync(0xffffffffu, mx0, 1));
        mx0 = fmaxf(mx0, __shfl_xor_sync(0xffffffffu, mx0, 2));
        mx1 = fmaxf(mx1, __shfl_xor_sync(0xffffffffu, mx1, 1));
        mx1 = fmaxf(mx1, __shfl_xor_sync(0xffffffffu, mx1, 2));
        float mn0 = fmaxf(m0, mx0), mn1 = fmaxf(m1, mx1);
        float s0 = 0.f, s1 = 0.f;
#pragma unroll
        for (int nt = 0; nt < 16; nt++) {
            S[nt][0] = ex2((S[nt][0] - mn0) * SCALE2);
            S[nt][1] = ex2((S[nt][1] - mn0) * SCALE2);
            S[nt][2] = ex2((S[nt][2] - mn1) * SCALE2);
            S[nt][3] = ex2((S[nt][3] - mn1) * SCALE2);
            s0 += S[nt][0] + S[nt][1];
            s1 += S[nt][2] + S[nt][3];
        }
        s0 += __shfl_xor_sync(0xffffffffu, s0, 1);
        s0 += __shfl_xor_sync(0xffffffffu, s0, 2);
        s1 += __shfl_xor_sync(0xffffffffu, s1, 1);
        s1 += __shfl_xor_sync(0xffffffffu, s1, 2);
        float a0 = ex2((m0 - mn0) * SCALE2);
        float a1 = ex2((m1 - mn1) * SCALE2);
        l0 = l0 * a0 + s0;
        l1 = l1 * a1 + s1;
        m0 = mn0; m1 = mn1;
#pragma unroll
        for (int nt = 0; nt < 8; nt++) {
            O[nt][0] *= a0; O[nt][1] *= a0;
            O[nt][2] *= a1; O[nt][3] *= a1;
        }

        // ---- O += P @ V  (V = K tile; P fragments from S via C->A layout identity) ----
#pragma unroll
        for (int kp = 0; kp < 8; kp++) {
            uint32_t ph[4], pl[4];
            cvt2(S[2 * kp][0],     S[2 * kp][1],     ph[0], pl[0]);
            cvt2(S[2 * kp][2],     S[2 * kp][3],     ph[1], pl[1]);
            cvt2(S[2 * kp + 1][0], S[2 * kp + 1][1], ph[2], pl[2]);
            cvt2(S[2 * kp + 1][2], S[2 * kp + 1][3], ph[3], pl[3]);
#pragma unroll
            for (int j2 = 0; j2 < 4; j2++) {
                uint32_t krow = (uint32_t)(kp * 16) + vka + vk7;
                uint32_t chn = (uint32_t)(j2 * 2) + vna;
                uint32_t ad = krow * 128 + ((chn ^ (krow & 7)) << 4);
                uint32_t vh[4], vl[4];
                ldsm4t(vh, Kh + ad);
                ldsm4t(vl, Kl + ad);
#pragma unroll
                for (int jj = 0; jj < 2; jj++) {
                    float* d = O[j2 * 2 + jj];
                    mma16816(d, ph, vh[jj], vh[2 + jj]);
                    mma16816(d, pl, vh[jj], vh[2 + jj]);
                    mma16816(d, ph, vl[jj], vl[2 + jj]);
                }
            }
        }
    }

    // ---- write normalized output ----
    float inv0 = 1.0f / l0, inv1 = 1.0f / l1;
    int r0 = l >> 2;
    int fb = (l & 3) * 2;
    float* op = out + gbase + (size_t)(q0 + w * 16) * DD;
#pragma unroll
    for (int nt = 0; nt < 8; nt++) {
        int f = nt * 8 + fb;
        *(float2*)(op + (size_t)r0 * DD + f) = make_float2(O[nt][0] * inv0, O[nt][1] * inv0);
        *(float2*)(op + (size_t)(r0 + 8) * DD + f) = make_float2(O[nt][2] * inv1, O[nt][3] * inv1);
    }
}

// ================= layernorm =================
__global__ __launch_bounds__(256) void ln_kernel(
    const float* __restrict__ in, const float* __restrict__ gw,
    const float* __restrict__ bw, float* __restrict__ out)
{
    const int row = blockIdx.x;
    const int tid = threadIdx.x;
    const float4 v = ((const float4*)(in + (size_t)row * DD))[tid];

    float s  = v.x + v.y + v.z + v.w;
    float sq = v.x * v.x + v.y * v.y + v.z * v.z + v.w * v.w;
#pragma unroll
    for (int off = 16; off > 0; off >>= 1) {
        s  += __shfl_down_sync(0xffffffffu, s,  off);
        sq += __shfl_down_sync(0xffffffffu, sq, off);
    }
    __shared__ float ssum[8], ssq[8];
    const int warp = tid / 32, lane = tid % 32;
    if (lane == 0) { ssum[warp] = s; ssq[warp] = sq; }
    __syncthreads();
    if (tid == 0) {
        float S = 0.f, Q = 0.f;
#pragma unroll
        for (int w = 0; w < 8; w++) { S += ssum[w]; Q += ssq[w]; }
        ssum[0] = S; ssq[0] = Q;
    }
    __syncthreads();
    const float mu  = ssum[0] * (1.0f / DD);
    const float var = ssq[0] * (1.0f / DD) - mu * mu;
    const float r   = rsqrtf(var + 1e-5f);

    const float4 g4 = ((const float4*)gw)[tid];
    const float4 b4 = ((const float4*)bw)[tid];
    float4 ov;
    ov.x = (v.x - mu) * r * g4.x + b4.x;
    ov.y = (v.y - mu) * r * g4.y + b4.y;
    ov.z = (v.z - mu) * r * g4.z + b4.z;
    ov.w = (v.w - mu) * r * g4.w + b4.w;
    ((float4*)(out + (size_t)row * DD))[tid] = ov;
}

// ================= launch =================
extern "C" void kernel_launch(void* const* d_in, const int* in_sizes, int n_in,
                              void* d_out, int out_size)
{
    const float* x     = (const float*)d_in[0];
    const float* wq_w  = (const float*)d_in[1];
    const float* wq_b  = (const float*)d_in[2];
    const float* fc_w  = (const float*)d_in[3];
    const float* fc_b  = (const float*)d_in[4];
    const float* ln1_g = (const float*)d_in[5];
    const float* ln1_b = (const float*)d_in[6];
    const float* w1    = (const float*)d_in[7];
    const float* b1    = (const float*)d_in[8];
    const float* w2    = (const float*)d_in[9];
    const float* b2    = (const float*)d_in[10];
    const float* ln2_g = (const float*)d_in[11];
    const float* ln2_b = (const float*)d_in[12];
    float* out = (float*)d_out;

    float *wq, *attn, *t1, *ln1, *hbuf, *t2;
    __nv_bfloat16 *whi, *wlo, *qhi, *qlo;
    cudaGetSymbolAddress((void**)&wq,   g_wq);
    cudaGetSymbolAddress((void**)&whi,  g_whi);
    cudaGetSymbolAddress((void**)&wlo,  g_wlo);
    cudaGetSymbolAddress((void**)&qhi,  g_qhi);
    cudaGetSymbolAddress((void**)&qlo,  g_qlo);
    cudaGetSymbolAddress((void**)&attn, g_attn);
    cudaGetSymbolAddress((void**)&t1,   g_t1);
    cudaGetSymbolAddress((void**)&ln1,  g_ln1);
    cudaGetSymbolAddress((void**)&hbuf, g_h);
    cudaGetSymbolAddress((void**)&t2,   g_t2);

    cudaFuncSetAttribute(hmma_gemm_kernel, cudaFuncAttributeMaxDynamicSharedMemorySize, HMMA_SMEM);
    cudaFuncSetAttribute(flash_hmma_kernel, cudaFuncAttributeMaxDynamicSharedMemorySize, FLASH_SMEM);

    // 1) pack Wq, then split all weights to bf16 hi/lo
    pack_wq_kernel<<<(DD * DD + 255) / 256, 256>>>(wq_w, wq);
    conv_split_kernel<<<(WSEG / 4 + 255) / 256, 256>>>(wq,   whi,            wlo,            WSEG / 4);
    conv_split_kernel<<<(WSEG / 4 + 255) / 256, 256>>>(fc_w, whi + WSEG,     wlo + WSEG,     WSEG / 4);
    conv_split_kernel<<<(WSEG + 255) / 256, 256>>>(w1,       whi + 2 * WSEG, wlo + 2 * WSEG, WSEG);
    conv_split_kernel<<<(WSEG + 255) / 256, 256>>>(w2,       whi + 6 * WSEG, wlo + 6 * WSEG, WSEG);

    // 2) qh = x @ Wq + wq_b  -> bf16 hi/lo split
    hmma_gemm_kernel<<<dim3(DD / 128, MROWS / 128), 512, HMMA_SMEM>>>(
        x, whi, wlo, wq_b, nullptr, nullptr, qhi, qlo, MROWS, DD, DD, 0);
    // 3) flash attention (HMMA)
    flash_hmma_kernel<<<dim3(SS / 128, HH, BB), 256, FLASH_SMEM>>>(qhi, qlo, attn);
    // 4) t1 = attn @ fc_w + fc_b + x
    hmma_gemm_kernel<<<dim3(DD / 128, MROWS / 128), 512, HMMA_SMEM>>>(
        attn, whi + WSEG, wlo + WSEG, fc_b, x, t1, nullptr, nullptr, MROWS, DD, DD, 0);
    // 5) ln1 = LN(t1)
    ln_kernel<<<MROWS, 256>>>(t1, ln1_g, ln1_b, ln1);
    // 6) h = relu(ln1 @ w1 + b1)
    hmma_gemm_kernel<<<dim3(D4 / 128, MROWS / 128), 512, HMMA_SMEM>>>(
        ln1, whi + 2 * WSEG, wlo + 2 * WSEG, b1, nullptr, hbuf, nullptr, nullptr, MROWS, D4, DD, 1);
    // 7) t2 = h @ w2 + b2 + ln1
    hmma_gemm_kernel<<<dim3(DD / 128, MROWS / 128), 512, HMMA_SMEM>>>(
        hbuf, whi + 6 * WSEG, wlo + 6 * WSEG, b2, ln1, t2, nullptr, nullptr, MROWS, DD, D4, 0);
    // 8) out = LN(t2)
    ln_kernel<<<MROWS, 256>>>(t2, ln2_g, ln2_b, out);
}

// round 5
// speedup vs baseline: 2.6176x; 1.1220x over previous
#include <cuda_runtime.h>
#include <cuda_bf16.h>
#include <cstdint>
#include <cstddef>

// Problem constants
#define BB 2
#define SS 2048
#define DD 1024
#define HH 16
#define DH 64
#define MROWS (BB*SS)          // 4096
#define D4 (4*DD)              // 4096
#define WSEG 1048576           // 1M elements per D*D weight

// ---------------- scratch (device globals; no allocations) ----------------
__device__ float g_wq  [DD*DD];                 // packed Wq fp32
__device__ __nv_bfloat16 g_whi[10*WSEG];        // wq | fc | w1 | w2 (hi)
__device__ __nv_bfloat16 g_wlo[10*WSEG];        // (lo)
__device__ __nv_bfloat16 g_xhi[MROWS*DD];       // x split
__device__ __nv_bfloat16 g_xlo[MROWS*DD];
__device__ __nv_bfloat16 g_qhi[MROWS*DD];       // qh split
__device__ __nv_bfloat16 g_qlo[MROWS*DD];
__device__ __nv_bfloat16 g_ahi[MROWS*DD];       // attn split
__device__ __nv_bfloat16 g_alo[MROWS*DD];
__device__ __nv_bfloat16 g_l1hi[MROWS*DD];      // ln1 split
__device__ __nv_bfloat16 g_l1lo[MROWS*DD];
__device__ __nv_bfloat16 g_hhi[MROWS*D4];       // mlp hidden split (relu'd)
__device__ __nv_bfloat16 g_hlo[MROWS*D4];
__device__ float g_t1  [MROWS*DD];
__device__ float g_ln1 [MROWS*DD];
__device__ float g_t2  [MROWS*DD];

// ================= helpers =================
__device__ __forceinline__ uint32_t smem_u32(const void* p) {
    uint32_t a;
    asm("{ .reg .u64 t; cvta.to.shared.u64 t, %1; cvt.u32.u64 %0, t; }" : "=r"(a) : "l"(p));
    return a;
}
__device__ __forceinline__ float ex2(float x) {
    float y; asm("ex2.approx.ftz.f32 %0, %1;" : "=f"(y) : "f"(x)); return y;
}
__device__ __forceinline__ void cvt2(float x, float y, uint32_t& hi, uint32_t& lo) {
    uint32_t h;
    asm("cvt.rn.bf16x2.f32 %0, %1, %2;" : "=r"(h) : "f"(y), "f"(x));
    float rx = x - __uint_as_float(h << 16);
    float ry = y - __uint_as_float(h & 0xffff0000u);
    asm("cvt.rn.bf16x2.f32 %0, %1, %2;" : "=r"(lo) : "f"(ry), "f"(rx));
    hi = h;
}
__device__ __forceinline__ void ldsm4(uint32_t* r, uint32_t addr) {
    asm volatile("ldmatrix.sync.aligned.m8n8.x4.shared.b16 {%0,%1,%2,%3}, [%4];"
                 : "=r"(r[0]), "=r"(r[1]), "=r"(r[2]), "=r"(r[3]) : "r"(addr));
}
__device__ __forceinline__ void ldsm4t(uint32_t* r, uint32_t addr) {
    asm volatile("ldmatrix.sync.aligned.m8n8.x4.trans.shared.b16 {%0,%1,%2,%3}, [%4];"
                 : "=r"(r[0]), "=r"(r[1]), "=r"(r[2]), "=r"(r[3]) : "r"(addr));
}
__device__ __forceinline__ void mma16816(float* d, const uint32_t* a, uint32_t b0, uint32_t b1) {
    asm volatile(
        "mma.sync.aligned.m16n8k16.row.col.f32.bf16.bf16.f32 "
        "{%0,%1,%2,%3}, {%4,%5,%6,%7}, {%8,%9}, {%0,%1,%2,%3};"
        : "+f"(d[0]), "+f"(d[1]), "+f"(d[2]), "+f"(d[3])
        : "r"(a[0]), "r"(a[1]), "r"(a[2]), "r"(a[3]), "r"(b0), "r"(b1));
}
__device__ __forceinline__ void cp16(uint32_t dst, const void* src) {
    asm volatile("cp.async.cg.shared.global [%0], [%1], 16;" :: "r"(dst), "l"(src) : "memory");
}
#define CP_COMMIT() asm volatile("cp.async.commit_group;" ::: "memory")
#define CP_WAIT0()  asm volatile("cp.async.wait_group 0;" ::: "memory")
#define CP_WAIT1()  asm volatile("cp.async.wait_group 1;" ::: "memory")
#define CP_WAIT2()  asm volatile("cp.async.wait_group 2;" ::: "memory")

// ================= pack wq_w [H,D,Dh] -> Wq [D, D] =================
__global__ void pack_wq_kernel(const float* __restrict__ wq_w, float* __restrict__ Wq) {
    int idx = blockIdx.x * blockDim.x + threadIdx.x;
    if (idx >= DD * DD) return;
    int d = idx / DD;
    int n = idx % DD;
    int h = n / DH;
    int e = n % DH;
    Wq[idx] = wq_w[((size_t)h * DD + d) * DH + e];
}

// ================= fp32 -> bf16 hi/lo splitter =================
__global__ void conv_split_kernel(const float* __restrict__ src,
                                  __nv_bfloat16* __restrict__ hi,
                                  __nv_bfloat16* __restrict__ lo, int n4) {
    int i = blockIdx.x * blockDim.x + threadIdx.x;
    if (i >= n4) return;
    float4 v = ((const float4*)src)[i];
    uint32_t h01, l01, h23, l23;
    cvt2(v.x, v.y, h01, l01);
    cvt2(v.z, v.w, h23, l23);
    uint32_t* hp = (uint32_t*)hi + (size_t)i * 2;
    uint32_t* lp = (uint32_t*)lo + (size_t)i * 2;
    hp[0] = h01; hp[1] = h23;
    lp[0] = l01; lp[1] = l23;
}

// ================= bf16x3 HMMA GEMM (512 threads, pure-bf16 A & B, 3-stage cp.async) =================
// C = A(bf16 hi/lo)[M,K] @ W(bf16 hi/lo)[K,N] (+bias) (+resid) (relu)
// fp32 output OR bf16 hi/lo split output (with optional relu).
#define STAGE_BYTES 32768
#define HMMA_SMEM (3 * STAGE_BYTES + 128)

__global__ __launch_bounds__(512, 1) void hmma_gemm_kernel(
    const __nv_bfloat16* __restrict__ Ahi_g, const __nv_bfloat16* __restrict__ Alo_g,
    const __nv_bfloat16* __restrict__ Whi, const __nv_bfloat16* __restrict__ Wlo,
    const float* __restrict__ bias, const float* __restrict__ resid,
    float* __restrict__ C, __nv_bfloat16* __restrict__ Chi, __nv_bfloat16* __restrict__ Clo,
    int M, int N, int K, int relu)
{
    extern __shared__ char dsm_raw[];
    uint32_t sraw = smem_u32(dsm_raw);
    uint32_t sb = (sraw + 127u) & ~127u;

    const int tid = threadIdx.x;
    const int wid = tid >> 5;
    const int l   = tid & 31;
    const int wm  = wid >> 2;     // 0..3
    const int wn  = wid & 3;      // 0..3
    const int row0 = blockIdx.y * 128;
    const int col0 = blockIdx.x * 128;

    float acc[8][4];
#pragma unroll
    for (int i = 0; i < 8; i++)
#pragma unroll
        for (int j = 0; j < 4; j++) acc[i][j] = 0.f;

    const int NS = K >> 5;

    // cp.async one full stage (A hi/lo + B hi/lo)
    const uint32_t ar = (uint32_t)tid >> 2, ac_ = (uint32_t)tid & 3;            // A: row, 16B chunk
    const uint32_t aoff = ar * 64 + ((ac_ ^ ((ar >> 1) & 3)) << 4);
    const uint32_t bk = (uint32_t)tid >> 4, bc = (uint32_t)tid & 15;            // B: k row, 16B chunk
    const uint32_t boff = bk * 256 + ((bc ^ (bk & 7)) << 4);

    auto cpStage = [&](int s) {
        uint32_t base = sb + (uint32_t)(s % 3) * STAGE_BYTES;
        int k0 = s << 5;
        const __nv_bfloat16* pah = Ahi_g + (size_t)(row0 + ar) * K + k0 + ac_ * 8;
        const __nv_bfloat16* pal = Alo_g + (size_t)(row0 + ar) * K + k0 + ac_ * 8;
        cp16(base + aoff, pah);
        cp16(base + 8192 + aoff, pal);
        const __nv_bfloat16* pbh = Whi + (size_t)(k0 + bk) * N + col0 + bc * 8;
        const __nv_bfloat16* pbl = Wlo + (size_t)(k0 + bk) * N + col0 + bc * 8;
        cp16(base + 16384 + boff, pbh);
        cp16(base + 24576 + boff, pbl);
        CP_COMMIT();
    };

    const uint32_t l15 = l & 15;
    const uint32_t ack = (uint32_t)(l >> 4);
    const uint32_t bk7 = (uint32_t)(l & 7);
    const uint32_t bka = (uint32_t)(l >> 4) * 8;
    const uint32_t bna = (uint32_t)((l >> 3) & 1) * 8;

    cpStage(0);
    if (NS > 1) cpStage(1);

    for (int s = 0; s < NS; s++) {
        __syncthreads();                 // protect reuse of buf (s+2)%3
        if (s + 2 < NS) { cpStage(s + 2); CP_WAIT2(); }
        else if (s + 1 < NS) { CP_WAIT1(); }
        else { CP_WAIT0(); }
        __syncthreads();                 // stage s visible to all warps

        uint32_t base = sb + (uint32_t)(s % 3) * STAGE_BYTES;
        uint32_t Ahi = base, Alo = base + 8192;
        uint32_t Bhi = base + 16384, Blo = base + 24576;

#pragma unroll
        for (int kk16 = 0; kk16 < 2; kk16++) {
            uint32_t ah[2][4], al[2][4], bh[2][4], bl[2][4];
            uint32_t ac = (uint32_t)(kk16 * 2) + ack;
#pragma unroll
            for (int i = 0; i < 2; i++) {
                uint32_t row = wm * 32 + i * 16 + l15;
                uint32_t ad = row * 64 + ((ac ^ ((row >> 1) & 3)) << 4);
                ldsm4(ah[i], Ahi + ad);
                ldsm4(al[i], Alo + ad);
            }
#pragma unroll
            for (int j2 = 0; j2 < 2; j2++) {
                uint32_t krow = (uint32_t)(kk16 * 16) + bka + bk7;
                uint32_t ncol = wn * 32 + j2 * 16 + bna;
                uint32_t bd = krow * 256 + (((ncol >> 3) ^ bk7) << 4);
                ldsm4t(bh[j2], Bhi + bd);
                ldsm4t(bl[j2], Blo + bd);
            }
#pragma unroll
            for (int i = 0; i < 2; i++) {
#pragma unroll
                for (int j = 0; j < 4; j++) {
                    int j2 = j >> 1, jj = j & 1;
                    float* d = acc[i * 4 + j];
                    mma16816(d, ah[i], bh[j2][jj], bh[j2][2 + jj]);
                    mma16816(d, ah[i], bl[j2][jj], bl[j2][2 + jj]);
                    mma16816(d, al[i], bh[j2][jj], bh[j2][2 + jj]);
                }
            }
        }
    }

    // ---- epilogue ----
    const int tq = l >> 2;
    const int tr = (l & 3) * 2;
#pragma unroll
    for (int j = 0; j < 4; j++) {
        int c = col0 + wn * 32 + j * 8 + tr;
        float bx = 0.f, by = 0.f;
        if (bias) { bx = bias[c]; by = bias[c + 1]; }
#pragma unroll
        for (int i = 0; i < 2; i++) {
            int m0 = row0 + wm * 32 + i * 16 + tq;
            float* d = acc[i * 4 + j];
            float v0x = d[0] + bx, v0y = d[1] + by;
            float v1x = d[2] + bx, v1y = d[3] + by;
            if (Chi) {
                if (relu) {
                    v0x = fmaxf(v0x, 0.f); v0y = fmaxf(v0y, 0.f);
                    v1x = fmaxf(v1x, 0.f); v1y = fmaxf(v1y, 0.f);
                }
                uint32_t h0, l0, h1, l1;
                cvt2(v0x, v0y, h0, l0);
                cvt2(v1x, v1y, h1, l1);
                *(uint32_t*)((uint16_t*)Chi + (size_t)m0 * N + c) = h0;
                *(uint32_t*)((uint16_t*)Clo + (size_t)m0 * N + c) = l0;
                *(uint32_t*)((uint16_t*)Chi + (size_t)(m0 + 8) * N + c) = h1;
                *(uint32_t*)((uint16_t*)Clo + (size_t)(m0 + 8) * N + c) = l1;
            } else {
                if (resid) {
                    float2 r0 = *(const float2*)(resid + (size_t)m0 * N + c);
                    float2 r1 = *(const float2*)(resid + (size_t)(m0 + 8) * N + c);
                    v0x += r0.x; v0y += r0.y; v1x += r1.x; v1y += r1.y;
                }
                if (relu) {
                    v0x = fmaxf(v0x, 0.f); v0y = fmaxf(v0y, 0.f);
                    v1x = fmaxf(v1x, 0.f); v1y = fmaxf(v1y, 0.f);
                }
                *(float2*)(C + (size_t)m0 * N + c) = make_float2(v0x, v0y);
                *(float2*)(C + (size_t)(m0 + 8) * N + c) = make_float2(v1x, v1y);
            }
        }
    }
}

// ================= flash attention, HMMA bf16x3 (Q=K=V) =================
// grid (S/128, H, B), 256 threads (8 warps x 16 queries). Keys in tiles of 128.
// Outputs attention in bf16 hi/lo split form.
#define FLASH_SMEM (96 * 1024 + 128)
#define SCALE2 0.18033688011112042f   /* log2(e)/8 */

__global__ __launch_bounds__(256, 1) void flash_hmma_kernel(
    const __nv_bfloat16* __restrict__ qhi, const __nv_bfloat16* __restrict__ qlo,
    __nv_bfloat16* __restrict__ ohi, __nv_bfloat16* __restrict__ olo)
{
    extern __shared__ char dsm_raw[];
    uint32_t sraw = smem_u32(dsm_raw);
    uint32_t sb = (sraw + 127u) & ~127u;

    const int tid = threadIdx.x;
    const int w   = tid >> 5;
    const int l   = tid & 31;
    const int q0  = blockIdx.x * 128;
    const int h   = blockIdx.y;
    const int b   = blockIdx.z;

    const uint32_t Qhi = sb, Qlo = sb + 16384;
    const size_t gbase = (size_t)b * SS * DD + h * DH;

    {
#pragma unroll
        for (int i = 0; i < 4; i++) {
            int idx = tid + i * 256;
            uint32_t r = idx >> 3, c = idx & 7;
            uint32_t off = r * 128 + ((c ^ (r & 7)) << 4);
            cp16(Qhi + off, qhi + gbase + (size_t)(q0 + r) * DD + c * 8);
            cp16(Qlo + off, qlo + gbase + (size_t)(q0 + r) * DD + c * 8);
            cp16(sb + 32768 + off, qhi + gbase + (size_t)r * DD + c * 8);
            cp16(sb + 32768 + 16384 + off, qlo + gbase + (size_t)r * DD + c * 8);
        }
        CP_COMMIT();
    }

    uint32_t aqh[4][4], aql[4][4];
    float S[16][4];
    float O[8][4];
    float m0 = -1e30f, m1 = -1e30f, l0 = 0.f, l1 = 0.f;
#pragma unroll
    for (int i = 0; i < 8; i++)
#pragma unroll
        for (int j = 0; j < 4; j++) O[i][j] = 0.f;

    const uint32_t l15 = l & 15;
    const uint32_t keyoff = (uint32_t)((l & 7) + ((l >> 3) & 1) * 8);
    const uint32_t kcadd  = (uint32_t)(l >> 4);
    const uint32_t vk7    = (uint32_t)(l & 7);
    const uint32_t vka    = (uint32_t)(l >> 4) * 8;
    const uint32_t vna    = (uint32_t)((l >> 3) & 1);

    const int NT = SS / 128;
    for (int kt = 0; kt < NT; kt++) {
        int p = kt & 1;
        __syncthreads();
        if (kt + 1 < NT) {
            uint32_t Kd = sb + 32768 + (uint32_t)(p ^ 1) * 32768u;
#pragma unroll
            for (int i = 0; i < 4; i++) {
                int idx = tid + i * 256;
                uint32_t r = idx >> 3, c = idx & 7;
                uint32_t off = r * 128 + ((c ^ (r & 7)) << 4);
                cp16(Kd + off, qhi + gbase + (size_t)((kt + 1) * 128 + r) * DD + c * 8);
                cp16(Kd + 16384 + off, qlo + gbase + (size_t)((kt + 1) * 128 + r) * DD + c * 8);
            }
            CP_COMMIT();
            CP_WAIT1();
        } else {
            CP_WAIT0();
        }
        __syncthreads();

        if (kt == 0) {
#pragma unroll
            for (int ks = 0; ks < 4; ks++) {
                uint32_t row = (uint32_t)(w * 16) + l15;
                uint32_t ch = (uint32_t)(ks * 2) + kcadd;
                uint32_t ad = row * 128 + ((ch ^ (row & 7)) << 4);
                ldsm4(aqh[ks], Qhi + ad);
                ldsm4(aql[ks], Qlo + ad);
            }
        }

        uint32_t Kh = sb + 32768 + (uint32_t)p * 32768u;
        uint32_t Kl = Kh + 16384;

        // ---- S = Q @ K^T ----
#pragma unroll
        for (int nt = 0; nt < 16; nt++)
#pragma unroll
            for (int c = 0; c < 4; c++) S[nt][c] = 0.f;
#pragma unroll
        for (int ks = 0; ks < 4; ks++) {
#pragma unroll
            for (int nb = 0; nb < 8; nb++) {
                uint32_t key = (uint32_t)(nb * 16) + keyoff;
                uint32_t ch = (uint32_t)(ks * 2) + kcadd;
                uint32_t ad = key * 128 + ((ch ^ (key & 7)) << 4);
                uint32_t bh[4], bl[4];
                ldsm4(bh, Kh + ad);
                ldsm4(bl, Kl + ad);
#pragma unroll
                for (int jj = 0; jj < 2; jj++) {
                    float* d = S[nb * 2 + jj];
                    mma16816(d, aqh[ks], bh[jj], bh[2 + jj]);
                    mma16816(d, aqh[ks], bl[jj], bl[2 + jj]);
                    mma16816(d, aql[ks], bh[jj], bh[2 + jj]);
                }
            }
        }

        // ---- online softmax ----
        float mx0 = -1e30f, mx1 = -1e30f;
#pragma unroll
        for (int nt = 0; nt < 16; nt++) {
            mx0 = fmaxf(mx0, fmaxf(S[nt][0], S[nt][1]));
            mx1 = fmaxf(mx1, fmaxf(S[nt][2], S[nt][3]));
        }
        mx0 = fmaxf(mx0, __shfl_xor_sync(0xffffffffu, mx0, 1));
        mx0 = fmaxf(mx0, __shfl_xor_sync(0xffffffffu, mx0, 2));
        mx1 = fmaxf(mx1, __shfl_xor_sync(0xffffffffu, mx1, 1));
        mx1 = fmaxf(mx1, __shfl_xor_sync(0xffffffffu, mx1, 2));
        float mn0 = fmaxf(m0, mx0), mn1 = fmaxf(m1, mx1);
        float s0 = 0.f, s1 = 0.f;
#pragma unroll
        for (int nt = 0; nt < 16; nt++) {
            S[nt][0] = ex2((S[nt][0] - mn0) * SCALE2);
            S[nt][1] = ex2((S[nt][1] - mn0) * SCALE2);
            S[nt][2] = ex2((S[nt][2] - mn1) * SCALE2);
            S[nt][3] = ex2((S[nt][3] - mn1) * SCALE2);
            s0 += S[nt][0] + S[nt][1];
            s1 += S[nt][2] + S[nt][3];
        }
        s0 += __shfl_xor_sync(0xffffffffu, s0, 1);
        s0 += __shfl_xor_sync(0xffffffffu, s0, 2);
        s1 += __shfl_xor_sync(0xffffffffu, s1, 1);
        s1 += __shfl_xor_sync(0xffffffffu, s1, 2);
        float a0 = ex2((m0 - mn0) * SCALE2);
        float a1 = ex2((m1 - mn1) * SCALE2);
        l0 = l0 * a0 + s0;
        l1 = l1 * a1 + s1;
        m0 = mn0; m1 = mn1;
#pragma unroll
        for (int nt = 0; nt < 8; nt++) {
            O[nt][0] *= a0; O[nt][1] *= a0;
            O[nt][2] *= a1; O[nt][3] *= a1;
        }

        // ---- O += P @ V ----
#pragma unroll
        for (int kp = 0; kp < 8; kp++) {
            uint32_t ph[4], pl[4];
            cvt2(S[2 * kp][0],     S[2 * kp][1],     ph[0], pl[0]);
            cvt2(S[2 * kp][2],     S[2 * kp][3],     ph[1], pl[1]);
            cvt2(S[2 * kp + 1][0], S[2 * kp + 1][1], ph[2], pl[2]);
            cvt2(S[2 * kp + 1][2], S[2 * kp + 1][3], ph[3], pl[3]);
#pragma unroll
            for (int j2 = 0; j2 < 4; j2++) {
                uint32_t krow = (uint32_t)(kp * 16) + vka + vk7;
                uint32_t chn = (uint32_t)(j2 * 2) + vna;
                uint32_t ad = krow * 128 + ((chn ^ (krow & 7)) << 4);
                uint32_t vh[4], vl[4];
                ldsm4t(vh, Kh + ad);
                ldsm4t(vl, Kl + ad);
#pragma unroll
                for (int jj = 0; jj < 2; jj++) {
                    float* d = O[j2 * 2 + jj];
                    mma16816(d, ph, vh[jj], vh[2 + jj]);
                    mma16816(d, pl, vh[jj], vh[2 + jj]);
                    mma16816(d, ph, vl[jj], vl[2 + jj]);
                }
            }
        }
    }

    // ---- write normalized output as bf16 hi/lo split ----
    float inv0 = 1.0f / l0, inv1 = 1.0f / l1;
    int r0 = l >> 2;
    int fb = (l & 3) * 2;
    uint16_t* oph = (uint16_t*)ohi + gbase + (size_t)(q0 + w * 16) * DD;
    uint16_t* opl = (uint16_t*)olo + gbase + (size_t)(q0 + w * 16) * DD;
#pragma unroll
    for (int nt = 0; nt < 8; nt++) {
        int f = nt * 8 + fb;
        uint32_t h0, lo0, h1, lo1;
        cvt2(O[nt][0] * inv0, O[nt][1] * inv0, h0, lo0);
        cvt2(O[nt][2] * inv1, O[nt][3] * inv1, h1, lo1);
        *(uint32_t*)(oph + (size_t)r0 * DD + f) = h0;
        *(uint32_t*)(opl + (size_t)r0 * DD + f) = lo0;
        *(uint32_t*)(oph + (size_t)(r0 + 8) * DD + f) = h1;
        *(uint32_t*)(opl + (size_t)(r0 + 8) * DD + f) = lo1;
    }
}

// ================= layernorm (optional bf16 hi/lo side output) =================
__global__ __launch_bounds__(256) void ln_kernel(
    const float* __restrict__ in, const float* __restrict__ gw,
    const float* __restrict__ bw, float* __restrict__ out,
    __nv_bfloat16* __restrict__ ohi, __nv_bfloat16* __restrict__ olo)
{
    const int row = blockIdx.x;
    const int tid = threadIdx.x;
    const float4 v = ((const float4*)(in + (size_t)row * DD))[tid];

    float s  = v.x + v.y + v.z + v.w;
    float sq = v.x * v.x + v.y * v.y + v.z * v.z + v.w * v.w;
#pragma unroll
    for (int off = 16; off > 0; off >>= 1) {
        s  += __shfl_down_sync(0xffffffffu, s,  off);
        sq += __shfl_down_sync(0xffffffffu, sq, off);
    }
    __shared__ float ssum[8], ssq[8];
    const int warp = tid / 32, lane = tid % 32;
    if (lane == 0) { ssum[warp] = s; ssq[warp] = sq; }
    __syncthreads();
    if (tid == 0) {
        float S = 0.f, Q = 0.f;
#pragma unroll
        for (int w = 0; w < 8; w++) { S += ssum[w]; Q += ssq[w]; }
        ssum[0] = S; ssq[0] = Q;
    }
    __syncthreads();
    const float mu  = ssum[0] * (1.0f / DD);
    const float var = ssq[0] * (1.0f / DD) - mu * mu;
    const float r   = rsqrtf(var + 1e-5f);

    const float4 g4 = ((const float4*)gw)[tid];
    const float4 b4 = ((const float4*)bw)[tid];
    float4 ov;
    ov.x = (v.x - mu) * r * g4.x + b4.x;
    ov.y = (v.y - mu) * r * g4.y + b4.y;
    ov.z = (v.z - mu) * r * g4.z + b4.z;
    ov.w = (v.w - mu) * r * g4.w + b4.w;
    ((float4*)(out + (size_t)row * DD))[tid] = ov;
    if (ohi) {
        uint32_t h01, l01, h23, l23;
        cvt2(ov.x, ov.y, h01, l01);
        cvt2(ov.z, ov.w, h23, l23);
        uint32_t* hp = (uint32_t*)ohi + (size_t)row * (DD / 2) + tid * 2;
        uint32_t* lp = (uint32_t*)olo + (size_t)row * (DD / 2) + tid * 2;
        hp[0] = h01; hp[1] = h23;
        lp[0] = l01; lp[1] = l23;
    }
}

// ================= launch =================
extern "C" void kernel_launch(void* const* d_in, const int* in_sizes, int n_in,
                              void* d_out, int out_size)
{
    const float* x     = (const float*)d_in[0];
    const float* wq_w  = (const float*)d_in[1];
    const float* wq_b  = (const float*)d_in[2];
    const float* fc_w  = (const float*)d_in[3];
    const float* fc_b  = (const float*)d_in[4];
    const float* ln1_g = (const float*)d_in[5];
    const float* ln1_b = (const float*)d_in[6];
    const float* w1    = (const float*)d_in[7];
    const float* b1    = (const float*)d_in[8];
    const float* w2    = (const float*)d_in[9];
    const float* b2    = (const float*)d_in[10];
    const float* ln2_g = (const float*)d_in[11];
    const float* ln2_b = (const float*)d_in[12];
    float* out = (float*)d_out;

    float *wq, *t1, *ln1, *t2;
    __nv_bfloat16 *whi, *wlo, *xhi, *xlo, *qhi, *qlo, *ahi, *alo, *l1hi, *l1lo, *hhi, *hlo;
    cudaGetSymbolAddress((void**)&wq,   g_wq);
    cudaGetSymbolAddress((void**)&whi,  g_whi);
    cudaGetSymbolAddress((void**)&wlo,  g_wlo);
    cudaGetSymbolAddress((void**)&xhi,  g_xhi);
    cudaGetSymbolAddress((void**)&xlo,  g_xlo);
    cudaGetSymbolAddress((void**)&qhi,  g_qhi);
    cudaGetSymbolAddress((void**)&qlo,  g_qlo);
    cudaGetSymbolAddress((void**)&ahi,  g_ahi);
    cudaGetSymbolAddress((void**)&alo,  g_alo);
    cudaGetSymbolAddress((void**)&l1hi, g_l1hi);
    cudaGetSymbolAddress((void**)&l1lo, g_l1lo);
    cudaGetSymbolAddress((void**)&hhi,  g_hhi);
    cudaGetSymbolAddress((void**)&hlo,  g_hlo);
    cudaGetSymbolAddress((void**)&t1,   g_t1);
    cudaGetSymbolAddress((void**)&ln1,  g_ln1);
    cudaGetSymbolAddress((void**)&t2,   g_t2);

    cudaFuncSetAttribute(hmma_gemm_kernel, cudaFuncAttributeMaxDynamicSharedMemorySize, HMMA_SMEM);
    cudaFuncSetAttribute(flash_hmma_kernel, cudaFuncAttributeMaxDynamicSharedMemorySize, FLASH_SMEM);

    // 1) pack Wq; split weights + x to bf16 hi/lo
    pack_wq_kernel<<<(DD * DD + 255) / 256, 256>>>(wq_w, wq);
    conv_split_kernel<<<(WSEG / 4 + 255) / 256, 256>>>(wq,   whi,            wlo,            WSEG / 4);
    conv_split_kernel<<<(WSEG / 4 + 255) / 256, 256>>>(fc_w, whi + WSEG,     wlo + WSEG,     WSEG / 4);
    conv_split_kernel<<<(WSEG + 255) / 256, 256>>>(w1,       whi + 2 * WSEG, wlo + 2 * WSEG, WSEG);
    conv_split_kernel<<<(WSEG + 255) / 256, 256>>>(w2,       whi + 6 * WSEG, wlo + 6 * WSEG, WSEG);
    conv_split_kernel<<<(MROWS * DD / 4 + 255) / 256, 256>>>(x, xhi, xlo, MROWS * DD / 4);

    // 2) qh = x @ Wq + wq_b  -> split
    hmma_gemm_kernel<<<dim3(DD / 128, MROWS / 128), 512, HMMA_SMEM>>>(
        xhi, xlo, whi, wlo, wq_b, nullptr, nullptr, qhi, qlo, MROWS, DD, DD, 0);
    // 3) flash attention -> split attn
    flash_hmma_kernel<<<dim3(SS / 128, HH, BB), 256, FLASH_SMEM>>>(qhi, qlo, ahi, alo);
    // 4) t1 = attn @ fc_w + fc_b + x (fp32)
    hmma_gemm_kernel<<<dim3(DD / 128, MROWS / 128), 512, HMMA_SMEM>>>(
        ahi, alo, whi + WSEG, wlo + WSEG, fc_b, x, t1, nullptr, nullptr, MROWS, DD, DD, 0);
    // 5) ln1 = LN(t1) (fp32 + split)
    ln_kernel<<<MROWS, 256>>>(t1, ln1_g, ln1_b, ln1, l1hi, l1lo);
    // 6) h = relu(ln1 @ w1 + b1) -> split
    hmma_gemm_kernel<<<dim3(D4 / 128, MROWS / 128), 512, HMMA_SMEM>>>(
        l1hi, l1lo, whi + 2 * WSEG, wlo + 2 * WSEG, b1, nullptr, nullptr, hhi, hlo, MROWS, D4, DD, 1);
    // 7) t2 = h @ w2 + b2 + ln1 (fp32)
    hmma_gemm_kernel<<<dim3(DD / 128, MROWS / 128), 512, HMMA_SMEM>>>(
        hhi, hlo, whi + 6 * WSEG, wlo + 6 * WSEG, b2, ln1, t2, nullptr, nullptr, MROWS, DD, D4, 0);
    // 8) out = LN(t2)
    ln_kernel<<<MROWS, 256>>>(t2, ln2_g, ln2_b, out, nullptr, nullptr);
}

// round 6
// speedup vs baseline: 6.0487x; 2.3108x over previous
#include <cuda_runtime.h>
#include <cuda_fp16.h>
#include <cstdint>
#include <cstddef>

// Problem constants
#define BB 2
#define SS 2048
#define DD 1024
#define HH 16
#define DH 64
#define MROWS (BB*SS)          // 4096
#define D4 (4*DD)              // 4096
#define WSEG 1048576           // 1M elements per D*D weight

// ---------------- scratch (device globals; no allocations) ----------------
__device__ __half g_wh [10*WSEG];     // wq | fc | w1 | w2 (fp16)
__device__ __half g_xh [MROWS*DD];    // x fp16
__device__ __half g_qh [MROWS*DD];    // q projection fp16
__device__ __half g_ah [MROWS*DD];    // attention out fp16
__device__ __half g_l1h[MROWS*DD];    // ln1 fp16
__device__ __half g_hh [MROWS*D4];    // mlp hidden fp16 (relu'd)
__device__ float  g_t1 [MROWS*DD];
__device__ float  g_ln1[MROWS*DD];
__device__ float  g_t2 [MROWS*DD];

// ================= helpers =================
__device__ __forceinline__ uint32_t smem_u32(const void* p) {
    uint32_t a;
    asm("{ .reg .u64 t; cvta.to.shared.u64 t, %1; cvt.u32.u64 %0, t; }" : "=r"(a) : "l"(p));
    return a;
}
__device__ __forceinline__ float ex2(float x) {
    float y; asm("ex2.approx.ftz.f32 %0, %1;" : "=f"(y) : "f"(x)); return y;
}
// pack two fp32 -> fp16x2 (x low, y high)
__device__ __forceinline__ uint32_t cvth2(float x, float y) {
    uint32_t h;
    asm("cvt.rn.f16x2.f32 %0, %1, %2;" : "=r"(h) : "f"(y), "f"(x));
    return h;
}
__device__ __forceinline__ void ldsm4(uint32_t* r, uint32_t addr) {
    asm volatile("ldmatrix.sync.aligned.m8n8.x4.shared.b16 {%0,%1,%2,%3}, [%4];"
                 : "=r"(r[0]), "=r"(r[1]), "=r"(r[2]), "=r"(r[3]) : "r"(addr));
}
__device__ __forceinline__ void ldsm4t(uint32_t* r, uint32_t addr) {
    asm volatile("ldmatrix.sync.aligned.m8n8.x4.trans.shared.b16 {%0,%1,%2,%3}, [%4];"
                 : "=r"(r[0]), "=r"(r[1]), "=r"(r[2]), "=r"(r[3]) : "r"(addr));
}
__device__ __forceinline__ void mma16816(float* d, const uint32_t* a, uint32_t b0, uint32_t b1) {
    asm volatile(
        "mma.sync.aligned.m16n8k16.row.col.f32.f16.f16.f32 "
        "{%0,%1,%2,%3}, {%4,%5,%6,%7}, {%8,%9}, {%0,%1,%2,%3};"
        : "+f"(d[0]), "+f"(d[1]), "+f"(d[2]), "+f"(d[3])
        : "r"(a[0]), "r"(a[1]), "r"(a[2]), "r"(a[3]), "r"(b0), "r"(b1));
}
__device__ __forceinline__ void cp16(uint32_t dst, const void* src) {
    asm volatile("cp.async.cg.shared.global [%0], [%1], 16;" :: "r"(dst), "l"(src) : "memory");
}
#define CP_COMMIT() asm volatile("cp.async.commit_group;" ::: "memory")
#define CP_WAIT0()  asm volatile("cp.async.wait_group 0;" ::: "memory")
#define CP_WAIT1()  asm volatile("cp.async.wait_group 1;" ::: "memory")
#define CP_WAIT2()  asm volatile("cp.async.wait_group 2;" ::: "memory")

// ================= pack wq_w [H,D,Dh] -> Wq fp16 [D, D] =================
__global__ void pack_wq_kernel(const float* __restrict__ wq_w, __half* __restrict__ Wq) {
    int idx = blockIdx.x * blockDim.x + threadIdx.x;
    if (idx >= DD * DD) return;
    int d = idx / DD;
    int n = idx % DD;
    int h = n / DH;
    int e = n % DH;
    Wq[idx] = __float2half_rn(wq_w[((size_t)h * DD + d) * DH + e]);
}

// ================= fp32 -> fp16 converter =================
__global__ void conv_f16_kernel(const float* __restrict__ src, __half* __restrict__ dst, int n4) {
    int i = blockIdx.x * blockDim.x + threadIdx.x;
    if (i >= n4) return;
    float4 v = ((const float4*)src)[i];
    uint2 o;
    o.x = cvth2(v.x, v.y);
    o.y = cvth2(v.z, v.w);
    ((uint2*)dst)[i] = o;
}

// ================= fp16 HMMA GEMM (512 threads, 3-stage cp.async) =================
// C = A(fp16)[M,K] @ W(fp16)[K,N] (+bias) (+resid) (relu); fp32 OR fp16 output.
#define STAGE_BYTES 16384
#define HMMA_SMEM (3 * STAGE_BYTES + 128)

__global__ __launch_bounds__(512, 1) void hmma_gemm_kernel(
    const __half* __restrict__ A, const __half* __restrict__ W,
    const float* __restrict__ bias, const float* __restrict__ resid,
    float* __restrict__ C, __half* __restrict__ Ch,
    int M, int N, int K, int relu)
{
    extern __shared__ char dsm_raw[];
    uint32_t sraw = smem_u32(dsm_raw);
    uint32_t sb = (sraw + 127u) & ~127u;

    const int tid = threadIdx.x;
    const int wid = tid >> 5;
    const int l   = tid & 31;
    const int wm  = wid >> 2;     // 0..3
    const int wn  = wid & 3;      // 0..3
    const int row0 = blockIdx.y * 128;
    const int col0 = blockIdx.x * 128;

    float acc[8][4];
#pragma unroll
    for (int i = 0; i < 8; i++)
#pragma unroll
        for (int j = 0; j < 4; j++) acc[i][j] = 0.f;

    const int NS = K >> 5;

    const uint32_t ar = (uint32_t)tid >> 2, ac_ = (uint32_t)tid & 3;
    const uint32_t aoff = ar * 64 + ((ac_ ^ ((ar >> 1) & 3)) << 4);
    const uint32_t bk = (uint32_t)tid >> 4, bc = (uint32_t)tid & 15;
    const uint32_t boff = bk * 256 + ((bc ^ (bk & 7)) << 4);

    auto cpStage = [&](int s) {
        uint32_t base = sb + (uint32_t)(s % 3) * STAGE_BYTES;
        int k0 = s << 5;
        cp16(base + aoff, A + (size_t)(row0 + ar) * K + k0 + ac_ * 8);
        cp16(base + 8192 + boff, W + (size_t)(k0 + bk) * N + col0 + bc * 8);
        CP_COMMIT();
    };

    const uint32_t l15 = l & 15;
    const uint32_t ack = (uint32_t)(l >> 4);
    const uint32_t bk7 = (uint32_t)(l & 7);
    const uint32_t bka = (uint32_t)(l >> 4) * 8;
    const uint32_t bna = (uint32_t)((l >> 3) & 1) * 8;

    cpStage(0);
    if (NS > 1) cpStage(1);

    for (int s = 0; s < NS; s++) {
        __syncthreads();                 // protect reuse of buf (s+2)%3
        if (s + 2 < NS) { cpStage(s + 2); CP_WAIT2(); }
        else if (s + 1 < NS) { CP_WAIT1(); }
        else { CP_WAIT0(); }
        __syncthreads();                 // stage s visible to all warps

        uint32_t base = sb + (uint32_t)(s % 3) * STAGE_BYTES;
        uint32_t Ab = base, Bb = base + 8192;

#pragma unroll
        for (int kk16 = 0; kk16 < 2; kk16++) {
            uint32_t ah[2][4], bh[2][4];
            uint32_t ac = (uint32_t)(kk16 * 2) + ack;
#pragma unroll
            for (int i = 0; i < 2; i++) {
                uint32_t row = wm * 32 + i * 16 + l15;
                uint32_t ad = row * 64 + ((ac ^ ((row >> 1) & 3)) << 4);
                ldsm4(ah[i], Ab + ad);
            }
#pragma unroll
            for (int j2 = 0; j2 < 2; j2++) {
                uint32_t krow = (uint32_t)(kk16 * 16) + bka + bk7;
                uint32_t ncol = wn * 32 + j2 * 16 + bna;
                uint32_t bd = krow * 256 + (((ncol >> 3) ^ bk7) << 4);
                ldsm4t(bh[j2], Bb + bd);
            }
#pragma unroll
            for (int i = 0; i < 2; i++) {
#pragma unroll
                for (int j = 0; j < 4; j++) {
                    int j2 = j >> 1, jj = j & 1;
                    mma16816(acc[i * 4 + j], ah[i], bh[j2][jj], bh[j2][2 + jj]);
                }
            }
        }
    }

    // ---- epilogue ----
    const int tq = l >> 2;
    const int tr = (l & 3) * 2;
#pragma unroll
    for (int j = 0; j < 4; j++) {
        int c = col0 + wn * 32 + j * 8 + tr;
        float bx = 0.f, by = 0.f;
        if (bias) { bx = bias[c]; by = bias[c + 1]; }
#pragma unroll
        for (int i = 0; i < 2; i++) {
            int m0 = row0 + wm * 32 + i * 16 + tq;
            float* d = acc[i * 4 + j];
            float v0x = d[0] + bx, v0y = d[1] + by;
            float v1x = d[2] + bx, v1y = d[3] + by;
            if (relu) {
                v0x = fmaxf(v0x, 0.f); v0y = fmaxf(v0y, 0.f);
                v1x = fmaxf(v1x, 0.f); v1y = fmaxf(v1y, 0.f);
            }
            if (Ch) {
                *(uint32_t*)((uint16_t*)Ch + (size_t)m0 * N + c) = cvth2(v0x, v0y);
                *(uint32_t*)((uint16_t*)Ch + (size_t)(m0 + 8) * N + c) = cvth2(v1x, v1y);
            } else {
                if (resid) {
                    float2 r0 = *(const float2*)(resid + (size_t)m0 * N + c);
                    float2 r1 = *(const float2*)(resid + (size_t)(m0 + 8) * N + c);
                    v0x += r0.x; v0y += r0.y; v1x += r1.x; v1y += r1.y;
                }
                *(float2*)(C + (size_t)m0 * N + c) = make_float2(v0x, v0y);
                *(float2*)(C + (size_t)(m0 + 8) * N + c) = make_float2(v1x, v1y);
            }
        }
    }
}

// ================= flash attention, fp16 HMMA (Q=K=V) =================
// grid (S/64, H, B), 128 threads (4 warps x 16 queries). Keys in tiles of 128.
// SMEM: Q (8K) | K buf0 (16K) | K buf1 (16K) = 40KB
#define FLASH_SMEM (40 * 1024 + 128)
#define SCALE2 0.18033688011112042f   /* log2(e)/8 */

__global__ __launch_bounds__(128, 3) void flash_hmma_kernel(
    const __half* __restrict__ qh, __half* __restrict__ oh)
{
    extern __shared__ char dsm_raw[];
    uint32_t sraw = smem_u32(dsm_raw);
    uint32_t sb = (sraw + 127u) & ~127u;

    const int tid = threadIdx.x;
    const int w   = tid >> 5;
    const int l   = tid & 31;
    const int q0  = blockIdx.x * 64;
    const int h   = blockIdx.y;
    const int b   = blockIdx.z;

    const uint32_t Qb = sb;
    const size_t gbase = (size_t)b * SS * DD + h * DH;

    // prologue: Q (64x64 fp16) + K tile 0 (128x64 fp16), one commit group
    {
#pragma unroll
        for (int i = 0; i < 4; i++) {
            int idx = tid + i * 128;
            uint32_t r = idx >> 3, c = idx & 7;
            uint32_t off = r * 128 + ((c ^ (r & 7)) << 4);
            cp16(Qb + off, qh + gbase + (size_t)(q0 + r) * DD + c * 8);
        }
#pragma unroll
        for (int i = 0; i < 8; i++) {
            int idx = tid + i * 128;
            uint32_t r = idx >> 3, c = idx & 7;
            uint32_t off = r * 128 + ((c ^ (r & 7)) << 4);
            cp16(sb + 8192 + off, qh + gbase + (size_t)r * DD + c * 8);
        }
        CP_COMMIT();
    }

    uint32_t aq[4][4];
    float S[16][4];
    float O[8][4];
    float m0 = -1e30f, m1 = -1e30f, l0 = 0.f, l1 = 0.f;
#pragma unroll
    for (int i = 0; i < 8; i++)
#pragma unroll
        for (int j = 0; j < 4; j++) O[i][j] = 0.f;

    const uint32_t l15 = l & 15;
    const uint32_t keyoff = (uint32_t)((l & 7) + ((l >> 3) & 1) * 8);
    const uint32_t kcadd  = (uint32_t)(l >> 4);
    const uint32_t vk7    = (uint32_t)(l & 7);
    const uint32_t vka    = (uint32_t)(l >> 4) * 8;
    const uint32_t vna    = (uint32_t)((l >> 3) & 1);

    const int NT = SS / 128;
    for (int kt = 0; kt < NT; kt++) {
        int p = kt & 1;
        __syncthreads();
        if (kt + 1 < NT) {
            uint32_t Kd = sb + 8192 + (uint32_t)(p ^ 1) * 16384u;
#pragma unroll
            for (int i = 0; i < 8; i++) {
                int idx = tid + i * 128;
                uint32_t r = idx >> 3, c = idx & 7;
                uint32_t off = r * 128 + ((c ^ (r & 7)) << 4);
                cp16(Kd + off, qh + gbase + (size_t)((kt + 1) * 128 + r) * DD + c * 8);
            }
            CP_COMMIT();
            CP_WAIT1();
        } else {
            CP_WAIT0();
        }
        __syncthreads();

        if (kt == 0) {
#pragma unroll
            for (int ks = 0; ks < 4; ks++) {
                uint32_t row = (uint32_t)(w * 16) + l15;
                uint32_t ch = (uint32_t)(ks * 2) + kcadd;
                uint32_t ad = row * 128 + ((ch ^ (row & 7)) << 4);
                ldsm4(aq[ks], Qb + ad);
            }
        }

        uint32_t Kb = sb + 8192 + (uint32_t)p * 16384u;

        // ---- S = Q @ K^T ----
#pragma unroll
        for (int nt = 0; nt < 16; nt++)
#pragma unroll
            for (int c = 0; c < 4; c++) S[nt][c] = 0.f;
#pragma unroll
        for (int ks = 0; ks < 4; ks++) {
#pragma unroll
            for (int nb = 0; nb < 8; nb++) {
                uint32_t key = (uint32_t)(nb * 16) + keyoff;
                uint32_t ch = (uint32_t)(ks * 2) + kcadd;
                uint32_t ad = key * 128 + ((ch ^ (key & 7)) << 4);
                uint32_t bh[4];
                ldsm4(bh, Kb + ad);
#pragma unroll
                for (int jj = 0; jj < 2; jj++)
                    mma16816(S[nb * 2 + jj], aq[ks], bh[jj], bh[2 + jj]);
            }
        }

        // ---- online softmax ----
        float mx0 = -1e30f, mx1 = -1e30f;
#pragma unroll
        for (int nt = 0; nt < 16; nt++) {
            mx0 = fmaxf(mx0, fmaxf(S[nt][0], S[nt][1]));
            mx1 = fmaxf(mx1, fmaxf(S[nt][2], S[nt][3]));
        }
        mx0 = fmaxf(mx0, __shfl_xor_sync(0xffffffffu, mx0, 1));
        mx0 = fmaxf(mx0, __shfl_xor_sync(0xffffffffu, mx0, 2));
        mx1 = fmaxf(mx1, __shfl_xor_sync(0xffffffffu, mx1, 1));
        mx1 = fmaxf(mx1, __shfl_xor_sync(0xffffffffu, mx1, 2));
        float mn0 = fmaxf(m0, mx0), mn1 = fmaxf(m1, mx1);
        float s0 = 0.f, s1 = 0.f;
#pragma unroll
        for (int nt = 0; nt < 16; nt++) {
            S[nt][0] = ex2((S[nt][0] - mn0) * SCALE2);
            S[nt][1] = ex2((S[nt][1] - mn0) * SCALE2);
            S[nt][2] = ex2((S[nt][2] - mn1) * SCALE2);
            S[nt][3] = ex2((S[nt][3] - mn1) * SCALE2);
            s0 += S[nt][0] + S[nt][1];
            s1 += S[nt][2] + S[nt][3];
        }
        s0 += __shfl_xor_sync(0xffffffffu, s0, 1);
        s0 += __shfl_xor_sync(0xffffffffu, s0, 2);
        s1 += __shfl_xor_sync(0xffffffffu, s1, 1);
        s1 += __shfl_xor_sync(0xffffffffu, s1, 2);
        float a0 = ex2((m0 - mn0) * SCALE2);
        float a1 = ex2((m1 - mn1) * SCALE2);
        l0 = l0 * a0 + s0;
        l1 = l1 * a1 + s1;
        m0 = mn0; m1 = mn1;
#pragma unroll
        for (int nt = 0; nt < 8; nt++) {
            O[nt][0] *= a0; O[nt][1] *= a0;
            O[nt][2] *= a1; O[nt][3] *= a1;
        }

        // ---- O += P @ V  (V = K tile; P fragments from S via C->A layout identity) ----
#pragma unroll
        for (int kp = 0; kp < 8; kp++) {
            uint32_t ph[4];
            ph[0] = cvth2(S[2 * kp][0],     S[2 * kp][1]);
            ph[1] = cvth2(S[2 * kp][2],     S[2 * kp][3]);
            ph[2] = cvth2(S[2 * kp + 1][0], S[2 * kp + 1][1]);
            ph[3] = cvth2(S[2 * kp + 1][2], S[2 * kp + 1][3]);
#pragma unroll
            for (int j2 = 0; j2 < 4; j2++) {
                uint32_t krow = (uint32_t)(kp * 16) + vka + vk7;
                uint32_t chn = (uint32_t)(j2 * 2) + vna;
                uint32_t ad = krow * 128 + ((chn ^ (krow & 7)) << 4);
                uint32_t vh[4];
                ldsm4t(vh, Kb + ad);
#pragma unroll
                for (int jj = 0; jj < 2; jj++)
                    mma16816(O[j2 * 2 + jj], ph, vh[jj], vh[2 + jj]);
            }
        }
    }

    // ---- write normalized output as fp16 ----
    float inv0 = 1.0f / l0, inv1 = 1.0f / l1;
    int r0 = l >> 2;
    int fb = (l & 3) * 2;
    uint16_t* op = (uint16_t*)oh + gbase + (size_t)(q0 + w * 16) * DD;
#pragma unroll
    for (int nt = 0; nt < 8; nt++) {
        int f = nt * 8 + fb;
        *(uint32_t*)(op + (size_t)r0 * DD + f) = cvth2(O[nt][0] * inv0, O[nt][1] * inv0);
        *(uint32_t*)(op + (size_t)(r0 + 8) * DD + f) = cvth2(O[nt][2] * inv1, O[nt][3] * inv1);
    }
}

// ================= layernorm (optional fp16 side output) =================
__global__ __launch_bounds__(256) void ln_kernel(
    const float* __restrict__ in, const float* __restrict__ gw,
    const float* __restrict__ bw, float* __restrict__ out,
    __half* __restrict__ oh)
{
    const int row = blockIdx.x;
    const int tid = threadIdx.x;
    const float4 v = ((const float4*)(in + (size_t)row * DD))[tid];

    float s  = v.x + v.y + v.z + v.w;
    float sq = v.x * v.x + v.y * v.y + v.z * v.z + v.w * v.w;
#pragma unroll
    for (int off = 16; off > 0; off >>= 1) {
        s  += __shfl_down_sync(0xffffffffu, s,  off);
        sq += __shfl_down_sync(0xffffffffu, sq, off);
    }
    __shared__ float ssum[8], ssq[8];
    const int warp = tid / 32, lane = tid % 32;
    if (lane == 0) { ssum[warp] = s; ssq[warp] = sq; }
    __syncthreads();
    if (tid == 0) {
        float S = 0.f, Q = 0.f;
#pragma unroll
        for (int w = 0; w < 8; w++) { S += ssum[w]; Q += ssq[w]; }
        ssum[0] = S; ssq[0] = Q;
    }
    __syncthreads();
    const float mu  = ssum[0] * (1.0f / DD);
    const float var = ssq[0] * (1.0f / DD) - mu * mu;
    const float r   = rsqrtf(var + 1e-5f);

    const float4 g4 = ((const float4*)gw)[tid];
    const float4 b4 = ((const float4*)bw)[tid];
    float4 ov;
    ov.x = (v.x - mu) * r * g4.x + b4.x;
    ov.y = (v.y - mu) * r * g4.y + b4.y;
    ov.z = (v.z - mu) * r * g4.z + b4.z;
    ov.w = (v.w - mu) * r * g4.w + b4.w;
    ((float4*)(out + (size_t)row * DD))[tid] = ov;
    if (oh) {
        uint2 o;
        o.x = cvth2(ov.x, ov.y);
        o.y = cvth2(ov.z, ov.w);
        ((uint2*)oh)[(size_t)row * (DD / 4) + tid] = o;
    }
}

// ================= launch =================
extern "C" void kernel_launch(void* const* d_in, const int* in_sizes, int n_in,
                              void* d_out, int out_size)
{
    const float* x     = (const float*)d_in[0];
    const float* wq_w  = (const float*)d_in[1];
    const float* wq_b  = (const float*)d_in[2];
    const float* fc_w  = (const float*)d_in[3];
    const float* fc_b  = (const float*)d_in[4];
    const float* ln1_g = (const float*)d_in[5];
    const float* ln1_b = (const float*)d_in[6];
    const float* w1    = (const float*)d_in[7];
    const float* b1    = (const float*)d_in[8];
    const float* w2    = (const float*)d_in[9];
    const float* b2    = (const float*)d_in[10];
    const float* ln2_g = (const float*)d_in[11];
    const float* ln2_b = (const float*)d_in[12];
    float* out = (float*)d_out;

    float *t1, *ln1, *t2;
    __half *wh, *xh, *qh, *ah, *l1h, *hh;
    cudaGetSymbolAddress((void**)&wh,  g_wh);
    cudaGetSymbolAddress((void**)&xh,  g_xh);
    cudaGetSymbolAddress((void**)&qh,  g_qh);
    cudaGetSymbolAddress((void**)&ah,  g_ah);
    cudaGetSymbolAddress((void**)&l1h, g_l1h);
    cudaGetSymbolAddress((void**)&hh,  g_hh);
    cudaGetSymbolAddress((void**)&t1,  g_t1);
    cudaGetSymbolAddress((void**)&ln1, g_ln1);
    cudaGetSymbolAddress((void**)&t2,  g_t2);

    cudaFuncSetAttribute(hmma_gemm_kernel, cudaFuncAttributeMaxDynamicSharedMemorySize, HMMA_SMEM);
    cudaFuncSetAttribute(flash_hmma_kernel, cudaFuncAttributeMaxDynamicSharedMemorySize, FLASH_SMEM);

    // 1) pack Wq (fp16); convert weights + x to fp16
    pack_wq_kernel<<<(DD * DD + 255) / 256, 256>>>(wq_w, wh);
    conv_f16_kernel<<<(WSEG / 4 + 255) / 256, 256>>>(fc_w, wh + WSEG, WSEG / 4);
    conv_f16_kernel<<<(WSEG + 255) / 256, 256>>>(w1, wh + 2 * WSEG, WSEG);
    conv_f16_kernel<<<(WSEG + 255) / 256, 256>>>(w2, wh + 6 * WSEG, WSEG);
    conv_f16_kernel<<<(MROWS * DD / 4 + 255) / 256, 256>>>(x, xh, MROWS * DD / 4);

    // 2) qh = x @ Wq + wq_b  (fp16 out)
    hmma_gemm_kernel<<<dim3(DD / 128, MROWS / 128), 512, HMMA_SMEM>>>(
        xh, wh, wq_b, nullptr, nullptr, qh, MROWS, DD, DD, 0);
    // 3) flash attention (fp16 out)
    flash_hmma_kernel<<<dim3(SS / 64, HH, BB), 128, FLASH_SMEM>>>(qh, ah);
    // 4) t1 = attn @ fc_w + fc_b + x (fp32)
    hmma_gemm_kernel<<<dim3(DD / 128, MROWS / 128), 512, HMMA_SMEM>>>(
        ah, wh + WSEG, fc_b, x, t1, nullptr, MROWS, DD, DD, 0);
    // 5) ln1 = LN(t1) (fp32 + fp16)
    ln_kernel<<<MROWS, 256>>>(t1, ln1_g, ln1_b, ln1, l1h);
    // 6) h = relu(ln1 @ w1 + b1) (fp16 out)
    hmma_gemm_kernel<<<dim3(D4 / 128, MROWS / 128), 512, HMMA_SMEM>>>(
        l1h, wh + 2 * WSEG, b1, nullptr, nullptr, hh, MROWS, D4, DD, 1);
    // 7) t2 = h @ w2 + b2 + ln1 (fp32)
    hmma_gemm_kernel<<<dim3(DD / 128, MROWS / 128), 512, HMMA_SMEM>>>(
        hh, wh + 6 * WSEG, b2, ln1, t2, nullptr, MROWS, DD, D4, 0);
    // 8) out = LN(t2)
    ln_kernel<<<MROWS, 256>>>(t2, ln2_g, ln2_b, out, nullptr);
}

// round 7
// speedup vs baseline: 6.8535x; 1.1331x over previous
#include <cuda_runtime.h>
#include <cuda_fp16.h>
#include <cstdint>
#include <cstddef>

// Problem constants
#define BB 2
#define SS 2048
#define DD 1024
#define HH 16
#define DH 64
#define MROWS (BB*SS)          // 4096
#define D4 (4*DD)              // 4096
#define WSEG 1048576           // 1M elements per D*D weight

// ---------------- scratch (device globals; no allocations) ----------------
__device__ __half g_wh [10*WSEG];     // wq | fc | w1 | w2 (fp16)
__device__ __half g_xh [MROWS*DD];    // x fp16
__device__ __half g_qh [MROWS*DD];    // q projection fp16
__device__ __half g_ah [MROWS*DD];    // attention out fp16
__device__ __half g_l1h[MROWS*DD];    // ln1 fp16
__device__ __half g_hh [MROWS*D4];    // mlp hidden fp16 (relu'd)
__device__ float  g_t1 [MROWS*DD];
__device__ float  g_ln1[MROWS*DD];
__device__ float  g_t2 [MROWS*DD];

// ================= helpers =================
__device__ __forceinline__ uint32_t smem_u32(const void* p) {
    uint32_t a;
    asm("{ .reg .u64 t; cvta.to.shared.u64 t, %1; cvt.u32.u64 %0, t; }" : "=r"(a) : "l"(p));
    return a;
}
__device__ __forceinline__ float ex2(float x) {
    float y; asm("ex2.approx.ftz.f32 %0, %1;" : "=f"(y) : "f"(x)); return y;
}
__device__ __forceinline__ uint32_t cvth2(float x, float y) {
    uint32_t h;
    asm("cvt.rn.f16x2.f32 %0, %1, %2;" : "=r"(h) : "f"(y), "f"(x));
    return h;
}
__device__ __forceinline__ void ldsm4(uint32_t* r, uint32_t addr) {
    asm volatile("ldmatrix.sync.aligned.m8n8.x4.shared.b16 {%0,%1,%2,%3}, [%4];"
                 : "=r"(r[0]), "=r"(r[1]), "=r"(r[2]), "=r"(r[3]) : "r"(addr));
}
__device__ __forceinline__ void ldsm4t(uint32_t* r, uint32_t addr) {
    asm volatile("ldmatrix.sync.aligned.m8n8.x4.trans.shared.b16 {%0,%1,%2,%3}, [%4];"
                 : "=r"(r[0]), "=r"(r[1]), "=r"(r[2]), "=r"(r[3]) : "r"(addr));
}
__device__ __forceinline__ void mma16816(float* d, const uint32_t* a, uint32_t b0, uint32_t b1) {
    asm volatile(
        "mma.sync.aligned.m16n8k16.row.col.f32.f16.f16.f32 "
        "{%0,%1,%2,%3}, {%4,%5,%6,%7}, {%8,%9}, {%0,%1,%2,%3};"
        : "+f"(d[0]), "+f"(d[1]), "+f"(d[2]), "+f"(d[3])
        : "r"(a[0]), "r"(a[1]), "r"(a[2]), "r"(a[3]), "r"(b0), "r"(b1));
}
__device__ __forceinline__ void cp16(uint32_t dst, const void* src) {
    asm volatile("cp.async.cg.shared.global [%0], [%1], 16;" :: "r"(dst), "l"(src) : "memory");
}
#define CP_COMMIT() asm volatile("cp.async.commit_group;" ::: "memory")
#define CP_WAIT0()  asm volatile("cp.async.wait_group 0;" ::: "memory")
#define CP_WAIT1()  asm volatile("cp.async.wait_group 1;" ::: "memory")
#define CP_WAIT2()  asm volatile("cp.async.wait_group 2;" ::: "memory")

// ================= pack wq_w [H,D,Dh] -> Wq fp16 [D, D] =================
__global__ void pack_wq_kernel(const float* __restrict__ wq_w, __half* __restrict__ Wq) {
    int idx = blockIdx.x * blockDim.x + threadIdx.x;
    if (idx >= DD * DD) return;
    int d = idx / DD;
    int n = idx % DD;
    int h = n / DH;
    int e = n % DH;
    Wq[idx] = __float2half_rn(wq_w[((size_t)h * DD + d) * DH + e]);
}

// ================= fp32 -> fp16 converter =================
__global__ void conv_f16_kernel(const float* __restrict__ src, __half* __restrict__ dst, int n4) {
    int i = blockIdx.x * blockDim.x + threadIdx.x;
    if (i >= n4) return;
    float4 v = ((const float4*)src)[i];
    uint2 o;
    o.x = cvth2(v.x, v.y);
    o.y = cvth2(v.z, v.w);
    ((uint2*)dst)[i] = o;
}

// ================= fp16 HMMA GEMM (256 threads, warp 64x32, 3-stage, 2 CTA/SM) ========
// C = A(fp16)[M,K] @ W(fp16)[K,N] (+bias) (+resid) (relu); fp32 OR fp16 output.
#define STAGE_BYTES 16384
#define HMMA_SMEM (3 * STAGE_BYTES + 128)

__global__ __launch_bounds__(256, 2) void hmma_gemm_kernel(
    const __half* __restrict__ A, const __half* __restrict__ W,
    const float* __restrict__ bias, const float* __restrict__ resid,
    float* __restrict__ C, __half* __restrict__ Ch,
    int M, int N, int K, int relu)
{
    extern __shared__ char dsm_raw[];
    uint32_t sraw = smem_u32(dsm_raw);
    uint32_t sb = (sraw + 127u) & ~127u;

    const int tid = threadIdx.x;
    const int wid = tid >> 5;
    const int l   = tid & 31;
    const int wm  = wid >> 2;     // 0..1 (m block of 64)
    const int wn  = wid & 3;      // 0..3 (n block of 32)
    const int row0 = blockIdx.y * 128;
    const int col0 = blockIdx.x * 128;

    float acc[16][4];
#pragma unroll
    for (int i = 0; i < 16; i++)
#pragma unroll
        for (int j = 0; j < 4; j++) acc[i][j] = 0.f;

    const int NS = K >> 5;

    // A: 128 rows x 32 fp16 (64B/row = 4 chunks). 512 chunks -> 2 per thread.
    // B: 32 rows x 128 fp16 (256B/row = 16 chunks). 512 chunks -> 2 per thread.
    auto cpStage = [&](int s) {
        uint32_t base = sb + (uint32_t)(s % 3) * STAGE_BYTES;
        int k0 = s << 5;
#pragma unroll
        for (int i = 0; i < 2; i++) {
            int idx = tid + i * 256;
            uint32_t r = (uint32_t)idx >> 2, c = (uint32_t)idx & 3;
            uint32_t aoff = r * 64 + ((c ^ ((r >> 1) & 3)) << 4);
            cp16(base + aoff, A + (size_t)(row0 + r) * K + k0 + c * 8);
        }
#pragma unroll
        for (int i = 0; i < 2; i++) {
            int idx = tid + i * 256;
            uint32_t k = (uint32_t)idx >> 4, c = (uint32_t)idx & 15;
            uint32_t boff = k * 256 + ((c ^ (k & 7)) << 4);
            cp16(base + 8192 + boff, W + (size_t)(k0 + k) * N + col0 + c * 8);
        }
        CP_COMMIT();
    };

    const uint32_t l15 = l & 15;
    const uint32_t ack = (uint32_t)(l >> 4);
    const uint32_t bk7 = (uint32_t)(l & 7);
    const uint32_t bka = (uint32_t)(l >> 4) * 8;
    const uint32_t bna = (uint32_t)((l >> 3) & 1) * 8;

    cpStage(0);
    if (NS > 1) cpStage(1);

    for (int s = 0; s < NS; s++) {
        __syncthreads();                 // protect reuse of buf (s+2)%3
        if (s + 2 < NS) { cpStage(s + 2); CP_WAIT2(); }
        else if (s + 1 < NS) { CP_WAIT1(); }
        else { CP_WAIT0(); }
        __syncthreads();                 // stage s visible

        uint32_t base = sb + (uint32_t)(s % 3) * STAGE_BYTES;
        uint32_t Ab = base, Bb = base + 8192;

#pragma unroll
        for (int kk16 = 0; kk16 < 2; kk16++) {
            uint32_t ah[4][4], bh[2][4];
            uint32_t ac = (uint32_t)(kk16 * 2) + ack;
#pragma unroll
            for (int i = 0; i < 4; i++) {
                uint32_t row = wm * 64 + i * 16 + l15;
                uint32_t ad = row * 64 + ((ac ^ ((row >> 1) & 3)) << 4);
                ldsm4(ah[i], Ab + ad);
            }
#pragma unroll
            for (int j2 = 0; j2 < 2; j2++) {
                uint32_t krow = (uint32_t)(kk16 * 16) + bka + bk7;
                uint32_t ncol = wn * 32 + j2 * 16 + bna;
                uint32_t bd = krow * 256 + (((ncol >> 3) ^ bk7) << 4);
                ldsm4t(bh[j2], Bb + bd);
            }
#pragma unroll
            for (int i = 0; i < 4; i++) {
#pragma unroll
                for (int j = 0; j < 4; j++) {
                    int j2 = j >> 1, jj = j & 1;
                    mma16816(acc[i * 4 + j], ah[i], bh[j2][jj], bh[j2][2 + jj]);
                }
            }
        }
    }

    // ---- epilogue ----
    const int tq = l >> 2;
    const int tr = (l & 3) * 2;
#pragma unroll
    for (int j = 0; j < 4; j++) {
        int c = col0 + wn * 32 + j * 8 + tr;
        float bx = 0.f, by = 0.f;
        if (bias) { bx = bias[c]; by = bias[c + 1]; }
#pragma unroll
        for (int i = 0; i < 4; i++) {
            int m0 = row0 + wm * 64 + i * 16 + tq;
            float* d = acc[i * 4 + j];
            float v0x = d[0] + bx, v0y = d[1] + by;
            float v1x = d[2] + bx, v1y = d[3] + by;
            if (relu) {
                v0x = fmaxf(v0x, 0.f); v0y = fmaxf(v0y, 0.f);
                v1x = fmaxf(v1x, 0.f); v1y = fmaxf(v1y, 0.f);
            }
            if (Ch) {
                *(uint32_t*)((uint16_t*)Ch + (size_t)m0 * N + c) = cvth2(v0x, v0y);
                *(uint32_t*)((uint16_t*)Ch + (size_t)(m0 + 8) * N + c) = cvth2(v1x, v1y);
            } else {
                if (resid) {
                    float2 r0 = *(const float2*)(resid + (size_t)m0 * N + c);
                    float2 r1 = *(const float2*)(resid + (size_t)(m0 + 8) * N + c);
                    v0x += r0.x; v0y += r0.y; v1x += r1.x; v1y += r1.y;
                }
                *(float2*)(C + (size_t)m0 * N + c) = make_float2(v0x, v0y);
                *(float2*)(C + (size_t)(m0 + 8) * N + c) = make_float2(v1x, v1y);
            }
        }
    }
}

// ================= flash attention, fp16 HMMA (Q=K=V) =================
// grid (S/64, H, B), 128 threads (4 warps x 16 queries). Keys in tiles of 128.
#define FLASH_SMEM (40 * 1024 + 128)
#define SCALE2 0.18033688011112042f   /* log2(e)/8 */

__global__ __launch_bounds__(128, 3) void flash_hmma_kernel(
    const __half* __restrict__ qh, __half* __restrict__ oh)
{
    extern __shared__ char dsm_raw[];
    uint32_t sraw = smem_u32(dsm_raw);
    uint32_t sb = (sraw + 127u) & ~127u;

    const int tid = threadIdx.x;
    const int w   = tid >> 5;
    const int l   = tid & 31;
    const int q0  = blockIdx.x * 64;
    const int h   = blockIdx.y;
    const int b   = blockIdx.z;

    const uint32_t Qb = sb;
    const size_t gbase = (size_t)b * SS * DD + h * DH;

    {
#pragma unroll
        for (int i = 0; i < 4; i++) {
            int idx = tid + i * 128;
            uint32_t r = idx >> 3, c = idx & 7;
            uint32_t off = r * 128 + ((c ^ (r & 7)) << 4);
            cp16(Qb + off, qh + gbase + (size_t)(q0 + r) * DD + c * 8);
        }
#pragma unroll
        for (int i = 0; i < 8; i++) {
            int idx = tid + i * 128;
            uint32_t r = idx >> 3, c = idx & 7;
            uint32_t off = r * 128 + ((c ^ (r & 7)) << 4);
            cp16(sb + 8192 + off, qh + gbase + (size_t)r * DD + c * 8);
        }
        CP_COMMIT();
    }

    uint32_t aq[4][4];
    float S[16][4];
    float O[8][4];
    float m0 = -1e30f, m1 = -1e30f, l0 = 0.f, l1 = 0.f;
#pragma unroll
    for (int i = 0; i < 8; i++)
#pragma unroll
        for (int j = 0; j < 4; j++) O[i][j] = 0.f;

    const uint32_t l15 = l & 15;
    const uint32_t keyoff = (uint32_t)((l & 7) + ((l >> 3) & 1) * 8);
    const uint32_t kcadd  = (uint32_t)(l >> 4);
    const uint32_t vk7    = (uint32_t)(l & 7);
    const uint32_t vka    = (uint32_t)(l >> 4) * 8;
    const uint32_t vna    = (uint32_t)((l >> 3) & 1);

    const int NT = SS / 128;
    for (int kt = 0; kt < NT; kt++) {
        int p = kt & 1;
        __syncthreads();
        if (kt + 1 < NT) {
            uint32_t Kd = sb + 8192 + (uint32_t)(p ^ 1) * 16384u;
#pragma unroll
            for (int i = 0; i < 8; i++) {
                int idx = tid + i * 128;
                uint32_t r = idx >> 3, c = idx & 7;
                uint32_t off = r * 128 + ((c ^ (r & 7)) << 4);
                cp16(Kd + off, qh + gbase + (size_t)((kt + 1) * 128 + r) * DD + c * 8);
            }
            CP_COMMIT();
            CP_WAIT1();
        } else {
            CP_WAIT0();
        }
        __syncthreads();

        if (kt == 0) {
#pragma unroll
            for (int ks = 0; ks < 4; ks++) {
                uint32_t row = (uint32_t)(w * 16) + l15;
                uint32_t ch = (uint32_t)(ks * 2) + kcadd;
                uint32_t ad = row * 128 + ((ch ^ (row & 7)) << 4);
                ldsm4(aq[ks], Qb + ad);
            }
        }

        uint32_t Kb = sb + 8192 + (uint32_t)p * 16384u;

        // ---- S = Q @ K^T ----
#pragma unroll
        for (int nt = 0; nt < 16; nt++)
#pragma unroll
            for (int c = 0; c < 4; c++) S[nt][c] = 0.f;
#pragma unroll
        for (int ks = 0; ks < 4; ks++) {
#pragma unroll
            for (int nb = 0; nb < 8; nb++) {
                uint32_t key = (uint32_t)(nb * 16) + keyoff;
                uint32_t ch = (uint32_t)(ks * 2) + kcadd;
                uint32_t ad = key * 128 + ((ch ^ (key & 7)) << 4);
                uint32_t bh[4];
                ldsm4(bh, Kb + ad);
#pragma unroll
                for (int jj = 0; jj < 2; jj++)
                    mma16816(S[nb * 2 + jj], aq[ks], bh[jj], bh[2 + jj]);
            }
        }

        // ---- online softmax ----
        float mx0 = -1e30f, mx1 = -1e30f;
#pragma unroll
        for (int nt = 0; nt < 16; nt++) {
            mx0 = fmaxf(mx0, fmaxf(S[nt][0], S[nt][1]));
            mx1 = fmaxf(mx1, fmaxf(S[nt][2], S[nt][3]));
        }
        mx0 = fmaxf(mx0, __shfl_xor_sync(0xffffffffu, mx0, 1));
        mx0 = fmaxf(mx0, __shfl_xor_sync(0xffffffffu, mx0, 2));
        mx1 = fmaxf(mx1, __shfl_xor_sync(0xffffffffu, mx1, 1));
        mx1 = fmaxf(mx1, __shfl_xor_sync(0xffffffffu, mx1, 2));
        float mn0 = fmaxf(m0, mx0), mn1 = fmaxf(m1, mx1);
        float s0 = 0.f, s1 = 0.f;
#pragma unroll
        for (int nt = 0; nt < 16; nt++) {
            S[nt][0] = ex2((S[nt][0] - mn0) * SCALE2);
            S[nt][1] = ex2((S[nt][1] - mn0) * SCALE2);
            S[nt][2] = ex2((S[nt][2] - mn1) * SCALE2);
            S[nt][3] = ex2((S[nt][3] - mn1) * SCALE2);
            s0 += S[nt][0] + S[nt][1];
            s1 += S[nt][2] + S[nt][3];
        }
        s0 += __shfl_xor_sync(0xffffffffu, s0, 1);
        s0 += __shfl_xor_sync(0xffffffffu, s0, 2);
        s1 += __shfl_xor_sync(0xffffffffu, s1, 1);
        s1 += __shfl_xor_sync(0xffffffffu, s1, 2);
        float a0 = ex2((m0 - mn0) * SCALE2);
        float a1 = ex2((m1 - mn1) * SCALE2);
        l0 = l0 * a0 + s0;
        l1 = l1 * a1 + s1;
        m0 = mn0; m1 = mn1;
#pragma unroll
        for (int nt = 0; nt < 8; nt++) {
            O[nt][0] *= a0; O[nt][1] *= a0;
            O[nt][2] *= a1; O[nt][3] *= a1;
        }

        // ---- O += P @ V ----
#pragma unroll
        for (int kp = 0; kp < 8; kp++) {
            uint32_t ph[4];
            ph[0] = cvth2(S[2 * kp][0],     S[2 * kp][1]);
            ph[1] = cvth2(S[2 * kp][2],     S[2 * kp][3]);
            ph[2] = cvth2(S[2 * kp + 1][0], S[2 * kp + 1][1]);
            ph[3] = cvth2(S[2 * kp + 1][2], S[2 * kp + 1][3]);
#pragma unroll
            for (int j2 = 0; j2 < 4; j2++) {
                uint32_t krow = (uint32_t)(kp * 16) + vka + vk7;
                uint32_t chn = (uint32_t)(j2 * 2) + vna;
                uint32_t ad = krow * 128 + ((chn ^ (krow & 7)) << 4);
                uint32_t vh[4];
                ldsm4t(vh, Kb + ad);
#pragma unroll
                for (int jj = 0; jj < 2; jj++)
                    mma16816(O[j2 * 2 + jj], ph, vh[jj], vh[2 + jj]);
            }
        }
    }

    // ---- write normalized output as fp16 ----
    float inv0 = 1.0f / l0, inv1 = 1.0f / l1;
    int r0 = l >> 2;
    int fb = (l & 3) * 2;
    uint16_t* op = (uint16_t*)oh + gbase + (size_t)(q0 + w * 16) * DD;
#pragma unroll
    for (int nt = 0; nt < 8; nt++) {
        int f = nt * 8 + fb;
        *(uint32_t*)(op + (size_t)r0 * DD + f) = cvth2(O[nt][0] * inv0, O[nt][1] * inv0);
        *(uint32_t*)(op + (size_t)(r0 + 8) * DD + f) = cvth2(O[nt][2] * inv1, O[nt][3] * inv1);
    }
}

// ================= layernorm (optional fp16 side output) =================
__global__ __launch_bounds__(256) void ln_kernel(
    const float* __restrict__ in, const float* __restrict__ gw,
    const float* __restrict__ bw, float* __restrict__ out,
    __half* __restrict__ oh)
{
    const int row = blockIdx.x;
    const int tid = threadIdx.x;
    const float4 v = ((const float4*)(in + (size_t)row * DD))[tid];

    float s  = v.x + v.y + v.z + v.w;
    float sq = v.x * v.x + v.y * v.y + v.z * v.z + v.w * v.w;
#pragma unroll
    for (int off = 16; off > 0; off >>= 1) {
        s  += __shfl_down_sync(0xffffffffu, s,  off);
        sq += __shfl_down_sync(0xffffffffu, sq, off);
    }
    __shared__ float ssum[8], ssq[8];
    const int warp = tid / 32, lane = tid % 32;
    if (lane == 0) { ssum[warp] = s; ssq[warp] = sq; }
    __syncthreads();
    if (tid == 0) {
        float S = 0.f, Q = 0.f;
#pragma unroll
        for (int w = 0; w < 8; w++) { S += ssum[w]; Q += ssq[w]; }
        ssum[0] = S; ssq[0] = Q;
    }
    __syncthreads();
    const float mu  = ssum[0] * (1.0f / DD);
    const float var = ssq[0] * (1.0f / DD) - mu * mu;
    const float r   = rsqrtf(var + 1e-5f);

    const float4 g4 = ((const float4*)gw)[tid];
    const float4 b4 = ((const float4*)bw)[tid];
    float4 ov;
    ov.x = (v.x - mu) * r * g4.x + b4.x;
    ov.y = (v.y - mu) * r * g4.y + b4.y;
    ov.z = (v.z - mu) * r * g4.z + b4.z;
    ov.w = (v.w - mu) * r * g4.w + b4.w;
    ((float4*)(out + (size_t)row * DD))[tid] = ov;
    if (oh) {
        uint2 o;
        o.x = cvth2(ov.x, ov.y);
        o.y = cvth2(ov.z, ov.w);
        ((uint2*)oh)[(size_t)row * (DD / 4) + tid] = o;
    }
}

// ================= launch =================
extern "C" void kernel_launch(void* const* d_in, const int* in_sizes, int n_in,
                              void* d_out, int out_size)
{
    const float* x     = (const float*)d_in[0];
    const float* wq_w  = (const float*)d_in[1];
    const float* wq_b  = (const float*)d_in[2];
    const float* fc_w  = (const float*)d_in[3];
    const float* fc_b  = (const float*)d_in[4];
    const float* ln1_g = (const float*)d_in[5];
    const float* ln1_b = (const float*)d_in[6];
    const float* w1    = (const float*)d_in[7];
    const float* b1    = (const float*)d_in[8];
    const float* w2    = (const float*)d_in[9];
    const float* b2    = (const float*)d_in[10];
    const float* ln2_g = (const float*)d_in[11];
    const float* ln2_b = (const float*)d_in[12];
    float* out = (float*)d_out;

    float *t1, *ln1, *t2;
    __half *wh, *xh, *qh, *ah, *l1h, *hh;
    cudaGetSymbolAddress((void**)&wh,  g_wh);
    cudaGetSymbolAddress((void**)&xh,  g_xh);
    cudaGetSymbolAddress((void**)&qh,  g_qh);
    cudaGetSymbolAddress((void**)&ah,  g_ah);
    cudaGetSymbolAddress((void**)&l1h, g_l1h);
    cudaGetSymbolAddress((void**)&hh,  g_hh);
    cudaGetSymbolAddress((void**)&t1,  g_t1);
    cudaGetSymbolAddress((void**)&ln1, g_ln1);
    cudaGetSymbolAddress((void**)&t2,  g_t2);

    cudaFuncSetAttribute(hmma_gemm_kernel, cudaFuncAttributeMaxDynamicSharedMemorySize, HMMA_SMEM);
    cudaFuncSetAttribute(flash_hmma_kernel, cudaFuncAttributeMaxDynamicSharedMemorySize, FLASH_SMEM);

    // 1) pack Wq (fp16); convert weights + x to fp16
    pack_wq_kernel<<<(DD * DD + 255) / 256, 256>>>(wq_w, wh);
    conv_f16_kernel<<<(WSEG / 4 + 255) / 256, 256>>>(fc_w, wh + WSEG, WSEG / 4);
    conv_f16_kernel<<<(WSEG + 255) / 256, 256>>>(w1, wh + 2 * WSEG, WSEG);
    conv_f16_kernel<<<(WSEG + 255) / 256, 256>>>(w2, wh + 6 * WSEG, WSEG);
    conv_f16_kernel<<<(MROWS * DD / 4 + 255) / 256, 256>>>(x, xh, MROWS * DD / 4);

    // 2) qh = x @ Wq + wq_b  (fp16 out)
    hmma_gemm_kernel<<<dim3(DD / 128, MROWS / 128), 256, HMMA_SMEM>>>(
        xh, wh, wq_b, nullptr, nullptr, qh, MROWS, DD, DD, 0);
    // 3) flash attention (fp16 out)
    flash_hmma_kernel<<<dim3(SS / 64, HH, BB), 128, FLASH_SMEM>>>(qh, ah);
    // 4) t1 = attn @ fc_w + fc_b + x (fp32)
    hmma_gemm_kernel<<<dim3(DD / 128, MROWS / 128), 256, HMMA_SMEM>>>(
        ah, wh + WSEG, fc_b, x, t1, nullptr, MROWS, DD, DD, 0);
    // 5) ln1 = LN(t1) (fp32 + fp16)
    ln_kernel<<<MROWS, 256>>>(t1, ln1_g, ln1_b, ln1, l1h);
    // 6) h = relu(ln1 @ w1 + b1) (fp16 out)
    hmma_gemm_kernel<<<dim3(D4 / 128, MROWS / 128), 256, HMMA_SMEM>>>(
        l1h, wh + 2 * WSEG, b1, nullptr, nullptr, hh, MROWS, D4, DD, 1);
    // 7) t2 = h @ w2 + b2 + ln1 (fp32)
    hmma_gemm_kernel<<<dim3(DD / 128, MROWS / 128), 256, HMMA_SMEM>>>(
        hh, wh + 6 * WSEG, b2, ln1, t2, nullptr, MROWS, DD, D4, 0);
    // 8) out = LN(t2)
    ln_kernel<<<MROWS, 256>>>(t2, ln2_g, ln2_b, out, nullptr);
}

// round 8
// speedup vs baseline: 7.1827x; 1.0480x over previous
#include <cuda_runtime.h>
#include <cuda_fp16.h>
#include <cstdint>
#include <cstddef>

// Problem constants
#define BB 2
#define SS 2048
#define DD 1024
#define HH 16
#define DH 64
#define MROWS (BB*SS)          // 4096
#define D4 (4*DD)              // 4096
#define WSEG 1048576           // 1M elements per D*D weight

// ---------------- scratch (device globals; no allocations) ----------------
__device__ __half g_wh [10*WSEG];     // wq | fc | w1 | w2 (fp16)
__device__ __half g_xh [MROWS*DD];    // x fp16
__device__ __half g_qh [MROWS*DD];    // q projection fp16
__device__ __half g_ah [MROWS*DD];    // attention out fp16
__device__ __half g_l1h[MROWS*DD];    // ln1 fp16
__device__ __half g_hh [MROWS*D4];    // mlp hidden fp16 (relu'd)
__device__ float  g_t1 [MROWS*DD];
__device__ float  g_ln1[MROWS*DD];
__device__ float  g_t2 [MROWS*DD];

// ================= helpers =================
__device__ __forceinline__ uint32_t smem_u32(const void* p) {
    uint32_t a;
    asm("{ .reg .u64 t; cvta.to.shared.u64 t, %1; cvt.u32.u64 %0, t; }" : "=r"(a) : "l"(p));
    return a;
}
__device__ __forceinline__ float ex2(float x) {
    float y; asm("ex2.approx.ftz.f32 %0, %1;" : "=f"(y) : "f"(x)); return y;
}
__device__ __forceinline__ uint32_t cvth2(float x, float y) {
    uint32_t h;
    asm("cvt.rn.f16x2.f32 %0, %1, %2;" : "=r"(h) : "f"(y), "f"(x));
    return h;
}
__device__ __forceinline__ void ldsm4(uint32_t* r, uint32_t addr) {
    asm volatile("ldmatrix.sync.aligned.m8n8.x4.shared.b16 {%0,%1,%2,%3}, [%4];"
                 : "=r"(r[0]), "=r"(r[1]), "=r"(r[2]), "=r"(r[3]) : "r"(addr));
}
__device__ __forceinline__ void ldsm4t(uint32_t* r, uint32_t addr) {
    asm volatile("ldmatrix.sync.aligned.m8n8.x4.trans.shared.b16 {%0,%1,%2,%3}, [%4];"
                 : "=r"(r[0]), "=r"(r[1]), "=r"(r[2]), "=r"(r[3]) : "r"(addr));
}
__device__ __forceinline__ void mma16816(float* d, const uint32_t* a, uint32_t b0, uint32_t b1) {
    asm volatile(
        "mma.sync.aligned.m16n8k16.row.col.f32.f16.f16.f32 "
        "{%0,%1,%2,%3}, {%4,%5,%6,%7}, {%8,%9}, {%0,%1,%2,%3};"
        : "+f"(d[0]), "+f"(d[1]), "+f"(d[2]), "+f"(d[3])
        : "r"(a[0]), "r"(a[1]), "r"(a[2]), "r"(a[3]), "r"(b0), "r"(b1));
}
__device__ __forceinline__ void cp16(uint32_t dst, const void* src) {
    asm volatile("cp.async.cg.shared.global [%0], [%1], 16;" :: "r"(dst), "l"(src) : "memory");
}
#define CP_COMMIT() asm volatile("cp.async.commit_group;" ::: "memory")
#define CP_WAIT0()  asm volatile("cp.async.wait_group 0;" ::: "memory")
#define CP_WAIT1()  asm volatile("cp.async.wait_group 1;" ::: "memory")
#define CP_WAIT2()  asm volatile("cp.async.wait_group 2;" ::: "memory")

// ================= pack wq_w [H,D,Dh] -> Wq fp16 [D, D] =================
__global__ void pack_wq_kernel(const float* __restrict__ wq_w, __half* __restrict__ Wq) {
    int idx = blockIdx.x * blockDim.x + threadIdx.x;
    if (idx >= DD * DD) return;
    int d = idx / DD;
    int n = idx % DD;
    int h = n / DH;
    int e = n % DH;
    Wq[idx] = __float2half_rn(wq_w[((size_t)h * DD + d) * DH + e]);
}

// ================= fp32 -> fp16 converter =================
__global__ void conv_f16_kernel(const float* __restrict__ src, __half* __restrict__ dst, int n4) {
    int i = blockIdx.x * blockDim.x + threadIdx.x;
    if (i >= n4) return;
    float4 v = ((const float4*)src)[i];
    uint2 o;
    o.x = cvth2(v.x, v.y);
    o.y = cvth2(v.z, v.w);
    ((uint2*)dst)[i] = o;
}

// ================= fp16 HMMA GEMM (256 threads, warp 64x32, K-stage 64, 3-stage) ======
// C = A(fp16)[M,K] @ W(fp16)[K,N] (+bias) (+resid) (relu); fp32 OR fp16 output.
// Stage: A 128x64 fp16 (16K, 128B rows, full 8-way swizzle) + B 64x128 fp16 (16K).
#define STAGE_BYTES 32768
#define HMMA_SMEM (3 * STAGE_BYTES + 128)

__global__ __launch_bounds__(256, 2) void hmma_gemm_kernel(
    const __half* __restrict__ A, const __half* __restrict__ W,
    const float* __restrict__ bias, const float* __restrict__ resid,
    float* __restrict__ C, __half* __restrict__ Ch,
    int M, int N, int K, int relu)
{
    extern __shared__ char dsm_raw[];
    uint32_t sraw = smem_u32(dsm_raw);
    uint32_t sb = (sraw + 127u) & ~127u;

    const int tid = threadIdx.x;
    const int wid = tid >> 5;
    const int l   = tid & 31;
    const int wm  = wid >> 2;     // 0..1 (m block of 64)
    const int wn  = wid & 3;      // 0..3 (n block of 32)
    const int row0 = blockIdx.y * 128;
    const int col0 = blockIdx.x * 128;

    float acc[16][4];
#pragma unroll
    for (int i = 0; i < 16; i++)
#pragma unroll
        for (int j = 0; j < 4; j++) acc[i][j] = 0.f;

    const int NS = K >> 6;   // K-stage 64

    // A: 128 rows x 64 fp16 (128B/row = 8 chunks) -> 1024 chunks, 4/thread
    // B: 64 rows x 128 fp16 (256B/row = 16 chunks) -> 1024 chunks, 4/thread
    auto cpStage = [&](int s) {
        uint32_t base = sb + (uint32_t)(s % 3) * STAGE_BYTES;
        int k0 = s << 6;
#pragma unroll
        for (int i = 0; i < 4; i++) {
            int idx = tid + i * 256;
            uint32_t r = (uint32_t)idx >> 3, c = (uint32_t)idx & 7;
            uint32_t aoff = r * 128 + ((c ^ (r & 7)) << 4);
            cp16(base + aoff, A + (size_t)(row0 + r) * K + k0 + c * 8);
        }
#pragma unroll
        for (int i = 0; i < 4; i++) {
            int idx = tid + i * 256;
            uint32_t k = (uint32_t)idx >> 4, c = (uint32_t)idx & 15;
            uint32_t boff = k * 256 + ((c ^ (k & 7)) << 4);
            cp16(base + 16384 + boff, W + (size_t)(k0 + k) * N + col0 + c * 8);
        }
        CP_COMMIT();
    };

    const uint32_t l15 = l & 15;
    const uint32_t ack = (uint32_t)(l >> 4);
    const uint32_t bk7 = (uint32_t)(l & 7);
    const uint32_t bka = (uint32_t)(l >> 4) * 8;
    const uint32_t bna = (uint32_t)((l >> 3) & 1) * 8;

    cpStage(0);
    if (NS > 1) cpStage(1);

    for (int s = 0; s < NS; s++) {
        __syncthreads();                 // protect reuse of buf (s+2)%3
        if (s + 2 < NS) { cpStage(s + 2); CP_WAIT2(); }
        else if (s + 1 < NS) { CP_WAIT1(); }
        else { CP_WAIT0(); }
        __syncthreads();                 // stage s visible

        uint32_t base = sb + (uint32_t)(s % 3) * STAGE_BYTES;
        uint32_t Ab = base, Bb = base + 16384;

#pragma unroll
        for (int kk16 = 0; kk16 < 4; kk16++) {
            uint32_t ah[4][4], bh[2][4];
            uint32_t ac = (uint32_t)(kk16 * 2) + ack;   // 0..7
#pragma unroll
            for (int i = 0; i < 4; i++) {
                uint32_t row = wm * 64 + i * 16 + l15;
                uint32_t ad = row * 128 + ((ac ^ (row & 7)) << 4);
                ldsm4(ah[i], Ab + ad);
            }
#pragma unroll
            for (int j2 = 0; j2 < 2; j2++) {
                uint32_t krow = (uint32_t)(kk16 * 16) + bka + bk7;   // 0..63, krow&7==bk7
                uint32_t ncol = wn * 32 + j2 * 16 + bna;
                uint32_t bd = krow * 256 + (((ncol >> 3) ^ bk7) << 4);
                ldsm4t(bh[j2], Bb + bd);
            }
#pragma unroll
            for (int i = 0; i < 4; i++) {
#pragma unroll
                for (int j = 0; j < 4; j++) {
                    int j2 = j >> 1, jj = j & 1;
                    mma16816(acc[i * 4 + j], ah[i], bh[j2][jj], bh[j2][2 + jj]);
                }
            }
        }
    }

    // ---- epilogue ----
    const int tq = l >> 2;
    const int tr = (l & 3) * 2;
#pragma unroll
    for (int j = 0; j < 4; j++) {
        int c = col0 + wn * 32 + j * 8 + tr;
        float bx = 0.f, by = 0.f;
        if (bias) { bx = bias[c]; by = bias[c + 1]; }
#pragma unroll
        for (int i = 0; i < 4; i++) {
            int m0 = row0 + wm * 64 + i * 16 + tq;
            float* d = acc[i * 4 + j];
            float v0x = d[0] + bx, v0y = d[1] + by;
            float v1x = d[2] + bx, v1y = d[3] + by;
            if (relu) {
                v0x = fmaxf(v0x, 0.f); v0y = fmaxf(v0y, 0.f);
                v1x = fmaxf(v1x, 0.f); v1y = fmaxf(v1y, 0.f);
            }
            if (Ch) {
                *(uint32_t*)((uint16_t*)Ch + (size_t)m0 * N + c) = cvth2(v0x, v0y);
                *(uint32_t*)((uint16_t*)Ch + (size_t)(m0 + 8) * N + c) = cvth2(v1x, v1y);
            } else {
                if (resid) {
                    float2 r0 = *(const float2*)(resid + (size_t)m0 * N + c);
                    float2 r1 = *(const float2*)(resid + (size_t)(m0 + 8) * N + c);
                    v0x += r0.x; v0y += r0.y; v1x += r1.x; v1y += r1.y;
                }
                *(float2*)(C + (size_t)m0 * N + c) = make_float2(v0x, v0y);
                *(float2*)(C + (size_t)(m0 + 8) * N + c) = make_float2(v1x, v1y);
            }
        }
    }
}

// ================= flash attention, fp16 HMMA (Q=K=V) =================
// grid (S/64, H, B), 128 threads (4 warps x 16 queries). Keys in tiles of 128.
#define FLASH_SMEM (40 * 1024 + 128)
#define SCALE2 0.18033688011112042f   /* log2(e)/8 */

__global__ __launch_bounds__(128, 3) void flash_hmma_kernel(
    const __half* __restrict__ qh, __half* __restrict__ oh)
{
    extern __shared__ char dsm_raw[];
    uint32_t sraw = smem_u32(dsm_raw);
    uint32_t sb = (sraw + 127u) & ~127u;

    const int tid = threadIdx.x;
    const int w   = tid >> 5;
    const int l   = tid & 31;
    const int q0  = blockIdx.x * 64;
    const int h   = blockIdx.y;
    const int b   = blockIdx.z;

    const uint32_t Qb = sb;
    const size_t gbase = (size_t)b * SS * DD + h * DH;

    {
#pragma unroll
        for (int i = 0; i < 4; i++) {
            int idx = tid + i * 128;
            uint32_t r = idx >> 3, c = idx & 7;
            uint32_t off = r * 128 + ((c ^ (r & 7)) << 4);
            cp16(Qb + off, qh + gbase + (size_t)(q0 + r) * DD + c * 8);
        }
#pragma unroll
        for (int i = 0; i < 8; i++) {
            int idx = tid + i * 128;
            uint32_t r = idx >> 3, c = idx & 7;
            uint32_t off = r * 128 + ((c ^ (r & 7)) << 4);
            cp16(sb + 8192 + off, qh + gbase + (size_t)r * DD + c * 8);
        }
        CP_COMMIT();
    }

    uint32_t aq[4][4];
    float S[16][4];
    float O[8][4];
    float m0 = -1e30f, m1 = -1e30f, l0 = 0.f, l1 = 0.f;
#pragma unroll
    for (int i = 0; i < 8; i++)
#pragma unroll
        for (int j = 0; j < 4; j++) O[i][j] = 0.f;

    const uint32_t l15 = l & 15;
    const uint32_t keyoff = (uint32_t)((l & 7) + ((l >> 3) & 1) * 8);
    const uint32_t kcadd  = (uint32_t)(l >> 4);
    const uint32_t vk7    = (uint32_t)(l & 7);
    const uint32_t vka    = (uint32_t)(l >> 4) * 8;
    const uint32_t vna    = (uint32_t)((l >> 3) & 1);

    const int NT = SS / 128;
    for (int kt = 0; kt < NT; kt++) {
        int p = kt & 1;
        __syncthreads();
        if (kt + 1 < NT) {
            uint32_t Kd = sb + 8192 + (uint32_t)(p ^ 1) * 16384u;
#pragma unroll
            for (int i = 0; i < 8; i++) {
                int idx = tid + i * 128;
                uint32_t r = idx >> 3, c = idx & 7;
                uint32_t off = r * 128 + ((c ^ (r & 7)) << 4);
                cp16(Kd + off, qh + gbase + (size_t)((kt + 1) * 128 + r) * DD + c * 8);
            }
            CP_COMMIT();
            CP_WAIT1();
        } else {
            CP_WAIT0();
        }
        __syncthreads();

        if (kt == 0) {
#pragma unroll
            for (int ks = 0; ks < 4; ks++) {
                uint32_t row = (uint32_t)(w * 16) + l15;
                uint32_t ch = (uint32_t)(ks * 2) + kcadd;
                uint32_t ad = row * 128 + ((ch ^ (row & 7)) << 4);
                ldsm4(aq[ks], Qb + ad);
            }
        }

        uint32_t Kb = sb + 8192 + (uint32_t)p * 16384u;

        // ---- S = Q @ K^T ----
#pragma unroll
        for (int nt = 0; nt < 16; nt++)
#pragma unroll
            for (int c = 0; c < 4; c++) S[nt][c] = 0.f;
#pragma unroll
        for (int ks = 0; ks < 4; ks++) {
#pragma unroll
            for (int nb = 0; nb < 8; nb++) {
                uint32_t key = (uint32_t)(nb * 16) + keyoff;
                uint32_t ch = (uint32_t)(ks * 2) + kcadd;
                uint32_t ad = key * 128 + ((ch ^ (key & 7)) << 4);
                uint32_t bh[4];
                ldsm4(bh, Kb + ad);
#pragma unroll
                for (int jj = 0; jj < 2; jj++)
                    mma16816(S[nb * 2 + jj], aq[ks], bh[jj], bh[2 + jj]);
            }
        }

        // ---- online softmax ----
        float mx0 = -1e30f, mx1 = -1e30f;
#pragma unroll
        for (int nt = 0; nt < 16; nt++) {
            mx0 = fmaxf(mx0, fmaxf(S[nt][0], S[nt][1]));
            mx1 = fmaxf(mx1, fmaxf(S[nt][2], S[nt][3]));
        }
        mx0 = fmaxf(mx0, __shfl_xor_sync(0xffffffffu, mx0, 1));
        mx0 = fmaxf(mx0, __shfl_xor_sync(0xffffffffu, mx0, 2));
        mx1 = fmaxf(mx1, __shfl_xor_sync(0xffffffffu, mx1, 1));
        mx1 = fmaxf(mx1, __shfl_xor_sync(0xffffffffu, mx1, 2));
        float mn0 = fmaxf(m0, mx0), mn1 = fmaxf(m1, mx1);
        float s0 = 0.f, s1 = 0.f;
#pragma unroll
        for (int nt = 0; nt < 16; nt++) {
            S[nt][0] = ex2((S[nt][0] - mn0) * SCALE2);
            S[nt][1] = ex2((S[nt][1] - mn0) * SCALE2);
            S[nt][2] = ex2((S[nt][2] - mn1) * SCALE2);
            S[nt][3] = ex2((S[nt][3] - mn1) * SCALE2);
            s0 += S[nt][0] + S[nt][1];
            s1 += S[nt][2] + S[nt][3];
        }
        s0 += __shfl_xor_sync(0xffffffffu, s0, 1);
        s0 += __shfl_xor_sync(0xffffffffu, s0, 2);
        s1 += __shfl_xor_sync(0xffffffffu, s1, 1);
        s1 += __shfl_xor_sync(0xffffffffu, s1, 2);
        float a0 = ex2((m0 - mn0) * SCALE2);
        float a1 = ex2((m1 - mn1) * SCALE2);
        l0 = l0 * a0 + s0;
        l1 = l1 * a1 + s1;
        m0 = mn0; m1 = mn1;
#pragma unroll
        for (int nt = 0; nt < 8; nt++) {
            O[nt][0] *= a0; O[nt][1] *= a0;
            O[nt][2] *= a1; O[nt][3] *= a1;
        }

        // ---- O += P @ V ----
#pragma unroll
        for (int kp = 0; kp < 8; kp++) {
            uint32_t ph[4];
            ph[0] = cvth2(S[2 * kp][0],     S[2 * kp][1]);
            ph[1] = cvth2(S[2 * kp][2],     S[2 * kp][3]);
            ph[2] = cvth2(S[2 * kp + 1][0], S[2 * kp + 1][1]);
            ph[3] = cvth2(S[2 * kp + 1][2], S[2 * kp + 1][3]);
#pragma unroll
            for (int j2 = 0; j2 < 4; j2++) {
                uint32_t krow = (uint32_t)(kp * 16) + vka + vk7;
                uint32_t chn = (uint32_t)(j2 * 2) + vna;
                uint32_t ad = krow * 128 + ((chn ^ (krow & 7)) << 4);
                uint32_t vh[4];
                ldsm4t(vh, Kb + ad);
#pragma unroll
                for (int jj = 0; jj < 2; jj++)
                    mma16816(O[j2 * 2 + jj], ph, vh[jj], vh[2 + jj]);
            }
        }
    }

    // ---- write normalized output as fp16 ----
    float inv0 = 1.0f / l0, inv1 = 1.0f / l1;
    int r0 = l >> 2;
    int fb = (l & 3) * 2;
    uint16_t* op = (uint16_t*)oh + gbase + (size_t)(q0 + w * 16) * DD;
#pragma unroll
    for (int nt = 0; nt < 8; nt++) {
        int f = nt * 8 + fb;
        *(uint32_t*)(op + (size_t)r0 * DD + f) = cvth2(O[nt][0] * inv0, O[nt][1] * inv0);
        *(uint32_t*)(op + (size_t)(r0 + 8) * DD + f) = cvth2(O[nt][2] * inv1, O[nt][3] * inv1);
    }
}

// ================= layernorm (optional fp16 side output) =================
__global__ __launch_bounds__(256) void ln_kernel(
    const float* __restrict__ in, const float* __restrict__ gw,
    const float* __restrict__ bw, float* __restrict__ out,
    __half* __restrict__ oh)
{
    const int row = blockIdx.x;
    const int tid = threadIdx.x;
    const float4 v = ((const float4*)(in + (size_t)row * DD))[tid];

    float s  = v.x + v.y + v.z + v.w;
    float sq = v.x * v.x + v.y * v.y + v.z * v.z + v.w * v.w;
#pragma unroll
    for (int off = 16; off > 0; off >>= 1) {
        s  += __shfl_down_sync(0xffffffffu, s,  off);
        sq += __shfl_down_sync(0xffffffffu, sq, off);
    }
    __shared__ float ssum[8], ssq[8];
    const int warp = tid / 32, lane = tid % 32;
    if (lane == 0) { ssum[warp] = s; ssq[warp] = sq; }
    __syncthreads();
    if (tid == 0) {
        float S = 0.f, Q = 0.f;
#pragma unroll
        for (int w = 0; w < 8; w++) { S += ssum[w]; Q += ssq[w]; }
        ssum[0] = S; ssq[0] = Q;
    }
    __syncthreads();
    const float mu  = ssum[0] * (1.0f / DD);
    const float var = ssq[0] * (1.0f / DD) - mu * mu;
    const float r   = rsqrtf(var + 1e-5f);

    const float4 g4 = ((const float4*)gw)[tid];
    const float4 b4 = ((const float4*)bw)[tid];
    float4 ov;
    ov.x = (v.x - mu) * r * g4.x + b4.x;
    ov.y = (v.y - mu) * r * g4.y + b4.y;
    ov.z = (v.z - mu) * r * g4.z + b4.z;
    ov.w = (v.w - mu) * r * g4.w + b4.w;
    ((float4*)(out + (size_t)row * DD))[tid] = ov;
    if (oh) {
        uint2 o;
        o.x = cvth2(ov.x, ov.y);
        o.y = cvth2(ov.z, ov.w);
        ((uint2*)oh)[(size_t)row * (DD / 4) + tid] = o;
    }
}

// ================= launch =================
extern "C" void kernel_launch(void* const* d_in, const int* in_sizes, int n_in,
                              void* d_out, int out_size)
{
    const float* x     = (const float*)d_in[0];
    const float* wq_w  = (const float*)d_in[1];
    const float* wq_b  = (const float*)d_in[2];
    const float* fc_w  = (const float*)d_in[3];
    const float* fc_b  = (const float*)d_in[4];
    const float* ln1_g = (const float*)d_in[5];
    const float* ln1_b = (const float*)d_in[6];
    const float* w1    = (const float*)d_in[7];
    const float* b1    = (const float*)d_in[8];
    const float* w2    = (const float*)d_in[9];
    const float* b2    = (const float*)d_in[10];
    const float* ln2_g = (const float*)d_in[11];
    const float* ln2_b = (const float*)d_in[12];
    float* out = (float*)d_out;

    float *t1, *ln1, *t2;
    __half *wh, *xh, *qh, *ah, *l1h, *hh;
    cudaGetSymbolAddress((void**)&wh,  g_wh);
    cudaGetSymbolAddress((void**)&xh,  g_xh);
    cudaGetSymbolAddress((void**)&qh,  g_qh);
    cudaGetSymbolAddress((void**)&ah,  g_ah);
    cudaGetSymbolAddress((void**)&l1h, g_l1h);
    cudaGetSymbolAddress((void**)&hh,  g_hh);
    cudaGetSymbolAddress((void**)&t1,  g_t1);
    cudaGetSymbolAddress((void**)&ln1, g_ln1);
    cudaGetSymbolAddress((void**)&t2,  g_t2);

    cudaFuncSetAttribute(hmma_gemm_kernel, cudaFuncAttributeMaxDynamicSharedMemorySize, HMMA_SMEM);
    cudaFuncSetAttribute(flash_hmma_kernel, cudaFuncAttributeMaxDynamicSharedMemorySize, FLASH_SMEM);

    // 1) pack Wq (fp16); convert weights + x to fp16
    pack_wq_kernel<<<(DD * DD + 255) / 256, 256>>>(wq_w, wh);
    conv_f16_kernel<<<(WSEG / 4 + 255) / 256, 256>>>(fc_w, wh + WSEG, WSEG / 4);
    conv_f16_kernel<<<(WSEG + 255) / 256, 256>>>(w1, wh + 2 * WSEG, WSEG);
    conv_f16_kernel<<<(WSEG + 255) / 256, 256>>>(w2, wh + 6 * WSEG, WSEG);
    conv_f16_kernel<<<(MROWS * DD / 4 + 255) / 256, 256>>>(x, xh, MROWS * DD / 4);

    // 2) qh = x @ Wq + wq_b  (fp16 out)
    hmma_gemm_kernel<<<dim3(DD / 128, MROWS / 128), 256, HMMA_SMEM>>>(
        xh, wh, wq_b, nullptr, nullptr, qh, MROWS, DD, DD, 0);
    // 3) flash attention (fp16 out)
    flash_hmma_kernel<<<dim3(SS / 64, HH, BB), 128, FLASH_SMEM>>>(qh, ah);
    // 4) t1 = attn @ fc_w + fc_b + x (fp32)
    hmma_gemm_kernel<<<dim3(DD / 128, MROWS / 128), 256, HMMA_SMEM>>>(
        ah, wh + WSEG, fc_b, x, t1, nullptr, MROWS, DD, DD, 0);
    // 5) ln1 = LN(t1) (fp32 + fp16)
    ln_kernel<<<MROWS, 256>>>(t1, ln1_g, ln1_b, ln1, l1h);
    // 6) h = relu(ln1 @ w1 + b1) (fp16 out)
    hmma_gemm_kernel<<<dim3(D4 / 128, MROWS / 128), 256, HMMA_SMEM>>>(
        l1h, wh + 2 * WSEG, b1, nullptr, nullptr, hh, MROWS, D4, DD, 1);
    // 7) t2 = h @ w2 + b2 + ln1 (fp32)
    hmma_gemm_kernel<<<dim3(DD / 128, MROWS / 128), 256, HMMA_SMEM>>>(
        hh, wh + 6 * WSEG, b2, ln1, t2, nullptr, MROWS, DD, D4, 0);
    // 8) out = LN(t2)
    ln_kernel<<<MROWS, 256>>>(t2, ln2_g, ln2_b, out, nullptr);
}